// round 1
// baseline (speedup 1.0000x reference)
#include <cuda_runtime.h>
#include <math.h>

#define D_MODEL 1024
#define N_HEADS 16
#define HEAD_DIM 64
#define BATCH 4
#define SEQ 2048
#define MROWS (BATCH * SEQ)          // 8192
#define QKV_N (3 * D_MODEL)          // 3072

// Scratch (allocation-free rule: __device__ globals)
__device__ float g_Q[BATCH * N_HEADS * SEQ * HEAD_DIM];   // [B,H,T,Dh]
__device__ float g_K[BATCH * N_HEADS * SEQ * HEAD_DIM];
__device__ float g_V[BATCH * N_HEADS * SEQ * HEAD_DIM];
__device__ float g_AO[MROWS * D_MODEL];                   // attention out, [B*T, C]

// ---------------------------------------------------------------------------
// SGEMM: C[M,N] = A[M,K] @ B[K,N] + bias[N]
// MODE 0: A = g_AO (read global scratch), write C param (final output)
// MODE 1: A = param (x), scatter into g_Q/g_K/g_V with [B,H,T,Dh] layout
// 128x128 block tile, BK=8, 256 threads, 8x8 per-thread register tile.
// ---------------------------------------------------------------------------
template <int MODE>
__global__ __launch_bounds__(256)
void sgemm_kernel(const float* __restrict__ A, const float* __restrict__ Bm,
                  const float* __restrict__ bias, float* __restrict__ C,
                  int M, int N, int K)
{
    constexpr int BM = 128, BN = 128, BK = 8, TM = 8, TN = 8;
    __shared__ float As[BK * BM];   // transposed
    __shared__ float Bs[BK * BN];

    const int tid = threadIdx.x;
    const int row0 = blockIdx.y * BM;
    const int col0 = blockIdx.x * BN;
    const int threadRow = tid / 16;
    const int threadCol = tid % 16;

    const int innerRowA = tid / 2;
    const int innerColA = (tid % 2) * 4;
    const int innerRowB = tid / 32;
    const int innerColB = (tid % 32) * 4;

    const float* Ap = (MODE == 0 ? (const float*)g_AO : A) + (size_t)row0 * K;
    const float* Bp = Bm + col0;

    float acc[TM][TN] = {};
    float regM[TM], regN[TN];

    for (int kt = 0; kt < K; kt += BK) {
        float4 av = *(const float4*)(Ap + (size_t)innerRowA * K + kt + innerColA);
        As[(innerColA + 0) * BM + innerRowA] = av.x;
        As[(innerColA + 1) * BM + innerRowA] = av.y;
        As[(innerColA + 2) * BM + innerRowA] = av.z;
        As[(innerColA + 3) * BM + innerRowA] = av.w;
        *(float4*)(Bs + innerRowB * BN + innerColB) =
            *(const float4*)(Bp + (size_t)(kt + innerRowB) * N + innerColB);
        __syncthreads();

        #pragma unroll
        for (int k = 0; k < BK; k++) {
            #pragma unroll
            for (int i = 0; i < TM; i++) regM[i] = As[k * BM + threadRow * TM + i];
            #pragma unroll
            for (int j = 0; j < TN; j++) regN[j] = Bs[k * BN + threadCol * TN + j];
            #pragma unroll
            for (int i = 0; i < TM; i++)
                #pragma unroll
                for (int j = 0; j < TN; j++)
                    acc[i][j] += regM[i] * regN[j];
        }
        __syncthreads();
    }

    // Epilogue
    #pragma unroll
    for (int i = 0; i < TM; i++) {
        const int m = row0 + threadRow * TM + i;
        #pragma unroll
        for (int j = 0; j < TN; j++) {
            const int n = col0 + threadCol * TN + j;
            const float val = acc[i][j] + bias[n];
            if (MODE == 0) {
                C[(size_t)m * N + n] = val;
            } else {
                // n in [0, 3072): section (q/k/v), head, dim; m -> (b, t)
                const int sec = n >> 10;
                const int c   = n & 1023;
                const int h   = c >> 6;
                const int d   = c & 63;
                const int b   = m >> 11;
                const int t   = m & 2047;
                const size_t dst = ((size_t)(b * N_HEADS + h) * SEQ + t) * HEAD_DIM + d;
                if (sec == 0)      g_Q[dst] = val;
                else if (sec == 1) g_K[dst] = val;
                else               g_V[dst] = val;
            }
        }
    }
}

// ---------------------------------------------------------------------------
// Flash attention, fp32, causal. One q-row per thread (128 rows per block),
// q and o accumulators in registers, K/V tiles (32 keys) broadcast from smem.
// Writes g_AO in [B*T, C] layout (h*64+d contiguous) for the out projection.
// ---------------------------------------------------------------------------
__global__ __launch_bounds__(128)
void flash_attn_kernel()
{
    constexpr int QT = 128, KT = 32;
    __shared__ float Ks[KT][HEAD_DIM];
    __shared__ float Vs[KT][HEAD_DIM];

    const int bh = blockIdx.y;           // b*16 + h
    const int b  = bh >> 4;
    const int h  = bh & 15;
    const int tq = blockIdx.x * QT + threadIdx.x;

    const float* Kbase = g_K + (size_t)bh * SEQ * HEAD_DIM;
    const float* Vbase = g_V + (size_t)bh * SEQ * HEAD_DIM;
    const float* qrow  = g_Q + ((size_t)bh * SEQ + tq) * HEAD_DIM;

    float q[HEAD_DIM];
    #pragma unroll
    for (int d = 0; d < HEAD_DIM; d += 4) {
        float4 v = *(const float4*)(qrow + d);
        q[d] = v.x; q[d + 1] = v.y; q[d + 2] = v.z; q[d + 3] = v.w;
    }

    float o[HEAD_DIM] = {};
    float mprev = -1e30f, l = 0.f;
    const float scale = 0.125f;          // 1/sqrt(64)

    const int nkt = (blockIdx.x + 1) * (QT / KT);   // causal: only tiles <= q tile end

    for (int kt = 0; kt < nkt; kt++) {
        const int kb = kt * KT;
        // cooperative tile load: 32x64 floats = 512 float4, 128 threads x 4
        #pragma unroll
        for (int i = 0; i < 4; i++) {
            const int c = threadIdx.x + i * 128;   // float4 index
            const int j = c >> 4;                  // 16 float4 per row
            const int d = (c & 15) * 4;
            *(float4*)(&Ks[j][d]) = *(const float4*)(Kbase + (size_t)(kb + j) * HEAD_DIM + d);
            *(float4*)(&Vs[j][d]) = *(const float4*)(Vbase + (size_t)(kb + j) * HEAD_DIM + d);
        }
        __syncthreads();

        float s[KT];
        float tmax = -1e30f;
        #pragma unroll 4
        for (int j = 0; j < KT; j++) {
            float a = 0.f;
            #pragma unroll
            for (int d = 0; d < HEAD_DIM; d++) a += q[d] * Ks[j][d];
            a *= scale;
            if (kb + j > tq) a = -1e30f;           // causal mask
            s[j] = a;
            tmax = fmaxf(tmax, a);
        }

        const float mnew = fmaxf(mprev, tmax);
        const float corr = __expf(mprev - mnew);
        l *= corr;
        #pragma unroll
        for (int d = 0; d < HEAD_DIM; d++) o[d] *= corr;

        #pragma unroll 2
        for (int j = 0; j < KT; j++) {
            const float p = __expf(s[j] - mnew);
            l += p;
            #pragma unroll
            for (int d = 0; d < HEAD_DIM; d++) o[d] += p * Vs[j][d];
        }
        mprev = mnew;
        __syncthreads();
    }

    const float inv = 1.f / l;
    float* orow = g_AO + ((size_t)(b * SEQ + tq)) * D_MODEL + h * HEAD_DIM;
    #pragma unroll
    for (int d = 0; d < HEAD_DIM; d += 4) {
        float4 v;
        v.x = o[d] * inv; v.y = o[d + 1] * inv;
        v.z = o[d + 2] * inv; v.w = o[d + 3] * inv;
        *(float4*)(orow + d) = v;
    }
}

// ---------------------------------------------------------------------------
extern "C" void kernel_launch(void* const* d_in, const int* in_sizes, int n_in,
                              void* d_out, int out_size)
{
    const float* x     = (const float*)d_in[0];
    const float* W_qkv = (const float*)d_in[1];
    const float* b_qkv = (const float*)d_in[2];
    const float* W_out = (const float*)d_in[3];
    const float* b_out = (const float*)d_in[4];
    float* out = (float*)d_out;

    // 1) QKV projection + scatter to [B,H,T,Dh]
    {
        dim3 grid(QKV_N / 128, MROWS / 128);   // (24, 64)
        sgemm_kernel<1><<<grid, 256>>>(x, W_qkv, b_qkv, nullptr,
                                       MROWS, QKV_N, D_MODEL);
    }
    // 2) Causal flash attention -> g_AO [B*T, C]
    {
        dim3 grid(SEQ / 128, BATCH * N_HEADS); // (16, 64)
        flash_attn_kernel<<<grid, 128>>>();
    }
    // 3) Output projection -> d_out
    {
        dim3 grid(D_MODEL / 128, MROWS / 128); // (8, 64)
        sgemm_kernel<0><<<grid, 256>>>(nullptr, W_out, b_out, out,
                                       MROWS, D_MODEL, D_MODEL);
    }
}

// round 2
// speedup vs baseline: 1.4752x; 1.4752x over previous
#include <cuda_runtime.h>
#include <math.h>
#include <stdint.h>

#define D_MODEL 1024
#define N_HEADS 16
#define HEAD_DIM 64
#define BATCH 4
#define SEQ 2048
#define MROWS (BATCH * SEQ)          // 8192
#define QKV_N (3 * D_MODEL)          // 3072

// Scratch (allocation-free rule: __device__ globals)
__device__ float g_Q[BATCH * N_HEADS * SEQ * HEAD_DIM];   // [B,H,T,Dh]
__device__ float g_K[BATCH * N_HEADS * SEQ * HEAD_DIM];
__device__ float g_V[BATCH * N_HEADS * SEQ * HEAD_DIM];
__device__ float g_AO[MROWS * D_MODEL];                   // attention out, [B*T, C]

__device__ __forceinline__ uint32_t f2tf(float f) {
    uint32_t u;
    asm("cvt.rna.tf32.f32 %0, %1;" : "=r"(u) : "f"(f));
    return u;
}

// ---------------------------------------------------------------------------
// TF32 tensor-core GEMM: C[M,N] = A[M,K] @ B[K,N] + bias[N]
// MODE 0: A = g_AO, write C (final output)
// MODE 1: A = param (x), scatter into g_Q/g_K/g_V with [B,H,T,Dh] layout
// 128x128 block tile, BK=16, 256 threads (8 warps, 4x2), warp tile 32x64,
// mma.sync.m16n8k8 tf32, double-buffered smem, register-staged loads.
// ---------------------------------------------------------------------------
template <int MODE>
__global__ __launch_bounds__(256)
void tgemm_kernel(const float* __restrict__ A, const float* __restrict__ Bm,
                  const float* __restrict__ bias, float* __restrict__ C,
                  int M, int N, int K)
{
    constexpr int BK = 16;
    constexpr int AST = 20;    // As row stride (conflict-free: bank = 20r+k spreads all lanes)
    constexpr int BST = 136;   // Bs row stride (bank = col + 8k, all 32 lanes distinct)

    __shared__ uint32_t As[2][128 * AST];
    __shared__ uint32_t Bs[2][BK * BST];

    const int tid   = threadIdx.x;
    const int wid   = tid >> 5;
    const int lane  = tid & 31;
    const int qr    = lane >> 2;     // 0..7
    const int qc    = lane & 3;      // 0..3
    const int warpM = wid >> 1;      // 0..3  (32 rows each)
    const int warpN = wid & 1;       // 0..1  (64 cols each)

    const int row0 = blockIdx.y * 128;
    const int col0 = blockIdx.x * 128;

    const float* Ap = (MODE == 0 ? (const float*)g_AO : A);

    // global load coords
    const int ra = tid >> 2;               // 0..63 (and +64)
    const int ka = (tid & 3) * 4;
    const int rb = tid >> 5;               // 0..7  (and +8)
    const int cb = (tid & 31) * 4;

    const float* Aload0 = Ap + (size_t)(row0 + ra) * K + ka;
    const float* Aload1 = Ap + (size_t)(row0 + ra + 64) * K + ka;
    const float* Bload0 = Bm + (size_t)rb * N + col0 + cb;
    const float* Bload1 = Bm + (size_t)(rb + 8) * N + col0 + cb;

    float acc[2][8][4] = {};

    const int NK = K / BK;

    float4 sa0, sa1, sb0, sb1;

    // prologue: tile 0 -> regs -> smem[0]
    sa0 = *(const float4*)(Aload0);
    sa1 = *(const float4*)(Aload1);
    sb0 = *(const float4*)(Bload0);
    sb1 = *(const float4*)(Bload1);
    {
        uint4 u;
        u.x = f2tf(sa0.x); u.y = f2tf(sa0.y); u.z = f2tf(sa0.z); u.w = f2tf(sa0.w);
        *(uint4*)&As[0][ra * AST + ka] = u;
        u.x = f2tf(sa1.x); u.y = f2tf(sa1.y); u.z = f2tf(sa1.z); u.w = f2tf(sa1.w);
        *(uint4*)&As[0][(ra + 64) * AST + ka] = u;
        u.x = f2tf(sb0.x); u.y = f2tf(sb0.y); u.z = f2tf(sb0.z); u.w = f2tf(sb0.w);
        *(uint4*)&Bs[0][rb * BST + cb] = u;
        u.x = f2tf(sb1.x); u.y = f2tf(sb1.y); u.z = f2tf(sb1.z); u.w = f2tf(sb1.w);
        *(uint4*)&Bs[0][(rb + 8) * BST + cb] = u;
    }
    __syncthreads();

    for (int kt = 0; kt < NK; kt++) {
        const int cur = kt & 1;
        // stage next tile into registers (overlaps with compute)
        if (kt + 1 < NK) {
            const int ko = (kt + 1) * BK;
            sa0 = *(const float4*)(Aload0 + ko);
            sa1 = *(const float4*)(Aload1 + ko);
            sb0 = *(const float4*)(Bload0 + (size_t)ko * N);
            sb1 = *(const float4*)(Bload1 + (size_t)ko * N);
        }

        // compute on buffer `cur`
        #pragma unroll
        for (int ks = 0; ks < 2; ks++) {
            const int k0 = ks * 8;
            uint32_t af[2][4], bf[8][2];
            #pragma unroll
            for (int mt = 0; mt < 2; mt++) {
                const int r = warpM * 32 + mt * 16 + qr;
                af[mt][0] = As[cur][r * AST + k0 + qc];
                af[mt][1] = As[cur][(r + 8) * AST + k0 + qc];
                af[mt][2] = As[cur][r * AST + k0 + qc + 4];
                af[mt][3] = As[cur][(r + 8) * AST + k0 + qc + 4];
            }
            #pragma unroll
            for (int nt = 0; nt < 8; nt++) {
                const int c = warpN * 64 + nt * 8 + qr;
                bf[nt][0] = Bs[cur][(k0 + qc) * BST + c];
                bf[nt][1] = Bs[cur][(k0 + qc + 4) * BST + c];
            }
            #pragma unroll
            for (int mt = 0; mt < 2; mt++)
                #pragma unroll
                for (int nt = 0; nt < 8; nt++) {
                    asm volatile(
                        "mma.sync.aligned.m16n8k8.row.col.f32.tf32.tf32.f32 "
                        "{%0,%1,%2,%3}, {%4,%5,%6,%7}, {%8,%9}, {%0,%1,%2,%3};\n"
                        : "+f"(acc[mt][nt][0]), "+f"(acc[mt][nt][1]),
                          "+f"(acc[mt][nt][2]), "+f"(acc[mt][nt][3])
                        : "r"(af[mt][0]), "r"(af[mt][1]), "r"(af[mt][2]), "r"(af[mt][3]),
                          "r"(bf[nt][0]), "r"(bf[nt][1]));
                }
        }

        // store staged tile into the other buffer
        if (kt + 1 < NK) {
            const int nxt = cur ^ 1;
            uint4 u;
            u.x = f2tf(sa0.x); u.y = f2tf(sa0.y); u.z = f2tf(sa0.z); u.w = f2tf(sa0.w);
            *(uint4*)&As[nxt][ra * AST + ka] = u;
            u.x = f2tf(sa1.x); u.y = f2tf(sa1.y); u.z = f2tf(sa1.z); u.w = f2tf(sa1.w);
            *(uint4*)&As[nxt][(ra + 64) * AST + ka] = u;
            u.x = f2tf(sb0.x); u.y = f2tf(sb0.y); u.z = f2tf(sb0.z); u.w = f2tf(sb0.w);
            *(uint4*)&Bs[nxt][rb * BST + cb] = u;
            u.x = f2tf(sb1.x); u.y = f2tf(sb1.y); u.z = f2tf(sb1.z); u.w = f2tf(sb1.w);
            *(uint4*)&Bs[nxt][(rb + 8) * BST + cb] = u;
        }
        __syncthreads();
    }

    // Epilogue. mma C layout: c0:(r,c) c1:(r,c+1) c2:(r+8,c) c3:(r+8,c+1)
    #pragma unroll
    for (int mt = 0; mt < 2; mt++) {
        const int r = row0 + warpM * 32 + mt * 16 + qr;
        #pragma unroll
        for (int nt = 0; nt < 8; nt++) {
            const int c = col0 + warpN * 64 + nt * 8 + 2 * qc;
            float v00 = acc[mt][nt][0] + bias[c];
            float v01 = acc[mt][nt][1] + bias[c + 1];
            float v10 = acc[mt][nt][2] + bias[c];
            float v11 = acc[mt][nt][3] + bias[c + 1];
            if (MODE == 0) {
                *(float2*)&C[(size_t)r * N + c]       = make_float2(v00, v01);
                *(float2*)&C[(size_t)(r + 8) * N + c] = make_float2(v10, v11);
            } else {
                #pragma unroll
                for (int e = 0; e < 4; e++) {
                    const int m = r + (e >> 1) * 8;
                    const int n = c + (e & 1);
                    const float val = (e == 0) ? v00 : (e == 1) ? v01 : (e == 2) ? v10 : v11;
                    const int sec = n >> 10;
                    const int cc  = n & 1023;
                    const int h   = cc >> 6;
                    const int d   = cc & 63;
                    const int b   = m >> 11;
                    const int t   = m & 2047;
                    const size_t dst = ((size_t)(b * N_HEADS + h) * SEQ + t) * HEAD_DIM + d;
                    if (sec == 0)      g_Q[dst] = val;
                    else if (sec == 1) g_K[dst] = val;
                    else               g_V[dst] = val;
                }
            }
        }
    }
}

// ---------------------------------------------------------------------------
// Flash attention, fp32, causal. One q-row per thread, float4 smem reads
// (4x fewer LDS instructions), scale folded into q, mask only on last tiles.
// ---------------------------------------------------------------------------
template <bool MASK>
__device__ __forceinline__ void attn_tile(
    const float (*Ks)[HEAD_DIM], const float (*Vs)[HEAD_DIM],
    const float* q, float* o, float& mprev, float& l, int kb, int tq)
{
    constexpr int KT = 32;
    float s[KT];
    float tmax = -1e30f;
    #pragma unroll 4
    for (int j = 0; j < KT; j++) {
        float a = 0.f;
        const float4* k4 = (const float4*)Ks[j];
        #pragma unroll
        for (int d4 = 0; d4 < HEAD_DIM / 4; d4++) {
            float4 kv = k4[d4];
            a += q[4 * d4]     * kv.x;
            a += q[4 * d4 + 1] * kv.y;
            a += q[4 * d4 + 2] * kv.z;
            a += q[4 * d4 + 3] * kv.w;
        }
        if (MASK && (kb + j > tq)) a = -1e30f;
        s[j] = a;
        tmax = fmaxf(tmax, a);
    }

    const float mnew = fmaxf(mprev, tmax);
    const float corr = __expf(mprev - mnew);
    l *= corr;
    #pragma unroll
    for (int d = 0; d < HEAD_DIM; d++) o[d] *= corr;

    #pragma unroll 2
    for (int j = 0; j < KT; j++) {
        const float p = __expf(s[j] - mnew);
        l += p;
        const float4* v4 = (const float4*)Vs[j];
        #pragma unroll
        for (int d4 = 0; d4 < HEAD_DIM / 4; d4++) {
            float4 vv = v4[d4];
            o[4 * d4]     += p * vv.x;
            o[4 * d4 + 1] += p * vv.y;
            o[4 * d4 + 2] += p * vv.z;
            o[4 * d4 + 3] += p * vv.w;
        }
    }
    mprev = mnew;
}

__global__ __launch_bounds__(128)
void flash_attn_kernel()
{
    constexpr int QT = 128, KT = 32;
    __shared__ float Ks[KT][HEAD_DIM];
    __shared__ float Vs[KT][HEAD_DIM];

    const int bh = blockIdx.y;           // b*16 + h
    const int b  = bh >> 4;
    const int h  = bh & 15;
    const int tq = blockIdx.x * QT + threadIdx.x;

    const float* Kbase = g_K + (size_t)bh * SEQ * HEAD_DIM;
    const float* Vbase = g_V + (size_t)bh * SEQ * HEAD_DIM;
    const float* qrow  = g_Q + ((size_t)bh * SEQ + tq) * HEAD_DIM;

    const float scale = 0.125f;          // 1/sqrt(64), folded into q
    float q[HEAD_DIM];
    #pragma unroll
    for (int d = 0; d < HEAD_DIM; d += 4) {
        float4 v = *(const float4*)(qrow + d);
        q[d] = v.x * scale; q[d + 1] = v.y * scale;
        q[d + 2] = v.z * scale; q[d + 3] = v.w * scale;
    }

    float o[HEAD_DIM] = {};
    float mprev = -1e30f, l = 0.f;

    const int fullTiles = blockIdx.x * (QT / KT);     // tiles with no masking
    const int nkt = fullTiles + (QT / KT);

    for (int kt = 0; kt < nkt; kt++) {
        const int kb = kt * KT;
        #pragma unroll
        for (int i = 0; i < 4; i++) {
            const int c = threadIdx.x + i * 128;
            const int j = c >> 4;
            const int d = (c & 15) * 4;
            *(float4*)(&Ks[j][d]) = *(const float4*)(Kbase + (size_t)(kb + j) * HEAD_DIM + d);
            *(float4*)(&Vs[j][d]) = *(const float4*)(Vbase + (size_t)(kb + j) * HEAD_DIM + d);
        }
        __syncthreads();

        if (kt < fullTiles)
            attn_tile<false>(Ks, Vs, q, o, mprev, l, kb, tq);
        else
            attn_tile<true>(Ks, Vs, q, o, mprev, l, kb, tq);

        __syncthreads();
    }

    const float inv = 1.f / l;
    float* orow = g_AO + ((size_t)(b * SEQ + tq)) * D_MODEL + h * HEAD_DIM;
    #pragma unroll
    for (int d = 0; d < HEAD_DIM; d += 4) {
        float4 v;
        v.x = o[d] * inv; v.y = o[d + 1] * inv;
        v.z = o[d + 2] * inv; v.w = o[d + 3] * inv;
        *(float4*)(orow + d) = v;
    }
}

// ---------------------------------------------------------------------------
extern "C" void kernel_launch(void* const* d_in, const int* in_sizes, int n_in,
                              void* d_out, int out_size)
{
    const float* x     = (const float*)d_in[0];
    const float* W_qkv = (const float*)d_in[1];
    const float* b_qkv = (const float*)d_in[2];
    const float* W_out = (const float*)d_in[3];
    const float* b_out = (const float*)d_in[4];
    float* out = (float*)d_out;

    // 1) QKV projection + scatter to [B,H,T,Dh]
    {
        dim3 grid(QKV_N / 128, MROWS / 128);   // (24, 64)
        tgemm_kernel<1><<<grid, 256>>>(x, W_qkv, b_qkv, nullptr,
                                       MROWS, QKV_N, D_MODEL);
    }
    // 2) Causal flash attention -> g_AO [B*T, C]
    {
        dim3 grid(SEQ / 128, BATCH * N_HEADS); // (16, 64)
        flash_attn_kernel<<<grid, 128>>>();
    }
    // 3) Output projection -> d_out
    {
        dim3 grid(D_MODEL / 128, MROWS / 128); // (8, 64)
        tgemm_kernel<0><<<grid, 256>>>(nullptr, W_out, b_out, out,
                                       MROWS, D_MODEL, D_MODEL);
    }
}

// round 3
// speedup vs baseline: 3.1571x; 2.1401x over previous
#include <cuda_runtime.h>
#include <math.h>
#include <stdint.h>

#define D_MODEL 1024
#define N_HEADS 16
#define HEAD_DIM 64
#define BATCH 4
#define SEQ 2048
#define MROWS (BATCH * SEQ)          // 8192
#define QKV_N (3 * D_MODEL)          // 3072

// Scratch (allocation-free rule: __device__ globals)
__device__ float g_Q[BATCH * N_HEADS * SEQ * HEAD_DIM];   // [B,H,T,Dh]
__device__ float g_K[BATCH * N_HEADS * SEQ * HEAD_DIM];
__device__ float g_V[BATCH * N_HEADS * SEQ * HEAD_DIM];
__device__ float g_AO[MROWS * D_MODEL];                   // attention out, [B*T, C]

__device__ __forceinline__ uint32_t f2tf(float f) {
    uint32_t u;
    asm("cvt.rna.tf32.f32 %0, %1;" : "=r"(u) : "f"(f));
    return u;
}
__device__ __forceinline__ float ex2(float x) {
    float r;
    asm("ex2.approx.f32 %0, %1;" : "=f"(r) : "f"(x));
    return r;
}
__device__ __forceinline__ void mma_tf32(float* d, const uint32_t* a,
                                         uint32_t b0, uint32_t b1) {
    asm volatile(
        "mma.sync.aligned.m16n8k8.row.col.f32.tf32.tf32.f32 "
        "{%0,%1,%2,%3}, {%4,%5,%6,%7}, {%8,%9}, {%0,%1,%2,%3};\n"
        : "+f"(d[0]), "+f"(d[1]), "+f"(d[2]), "+f"(d[3])
        : "r"(a[0]), "r"(a[1]), "r"(a[2]), "r"(a[3]), "r"(b0), "r"(b1));
}

// ---------------------------------------------------------------------------
// TF32 tensor-core GEMM (unchanged from round 2)
// ---------------------------------------------------------------------------
template <int MODE>
__global__ __launch_bounds__(256)
void tgemm_kernel(const float* __restrict__ A, const float* __restrict__ Bm,
                  const float* __restrict__ bias, float* __restrict__ C,
                  int M, int N, int K)
{
    constexpr int BK = 16;
    constexpr int AST = 20;
    constexpr int BST = 136;

    __shared__ uint32_t As[2][128 * AST];
    __shared__ uint32_t Bs[2][BK * BST];

    const int tid   = threadIdx.x;
    const int wid   = tid >> 5;
    const int lane  = tid & 31;
    const int qr    = lane >> 2;
    const int qc    = lane & 3;
    const int warpM = wid >> 1;
    const int warpN = wid & 1;

    const int row0 = blockIdx.y * 128;
    const int col0 = blockIdx.x * 128;

    const float* Ap = (MODE == 0 ? (const float*)g_AO : A);

    const int ra = tid >> 2;
    const int ka = (tid & 3) * 4;
    const int rb = tid >> 5;
    const int cb = (tid & 31) * 4;

    const float* Aload0 = Ap + (size_t)(row0 + ra) * K + ka;
    const float* Aload1 = Ap + (size_t)(row0 + ra + 64) * K + ka;
    const float* Bload0 = Bm + (size_t)rb * N + col0 + cb;
    const float* Bload1 = Bm + (size_t)(rb + 8) * N + col0 + cb;

    float acc[2][8][4] = {};
    const int NK = K / BK;
    float4 sa0, sa1, sb0, sb1;

    sa0 = *(const float4*)(Aload0);
    sa1 = *(const float4*)(Aload1);
    sb0 = *(const float4*)(Bload0);
    sb1 = *(const float4*)(Bload1);
    {
        uint4 u;
        u.x = f2tf(sa0.x); u.y = f2tf(sa0.y); u.z = f2tf(sa0.z); u.w = f2tf(sa0.w);
        *(uint4*)&As[0][ra * AST + ka] = u;
        u.x = f2tf(sa1.x); u.y = f2tf(sa1.y); u.z = f2tf(sa1.z); u.w = f2tf(sa1.w);
        *(uint4*)&As[0][(ra + 64) * AST + ka] = u;
        u.x = f2tf(sb0.x); u.y = f2tf(sb0.y); u.z = f2tf(sb0.z); u.w = f2tf(sb0.w);
        *(uint4*)&Bs[0][rb * BST + cb] = u;
        u.x = f2tf(sb1.x); u.y = f2tf(sb1.y); u.z = f2tf(sb1.z); u.w = f2tf(sb1.w);
        *(uint4*)&Bs[0][(rb + 8) * BST + cb] = u;
    }
    __syncthreads();

    for (int kt = 0; kt < NK; kt++) {
        const int cur = kt & 1;
        if (kt + 1 < NK) {
            const int ko = (kt + 1) * BK;
            sa0 = *(const float4*)(Aload0 + ko);
            sa1 = *(const float4*)(Aload1 + ko);
            sb0 = *(const float4*)(Bload0 + (size_t)ko * N);
            sb1 = *(const float4*)(Bload1 + (size_t)ko * N);
        }

        #pragma unroll
        for (int ks = 0; ks < 2; ks++) {
            const int k0 = ks * 8;
            uint32_t af[2][4], bf[8][2];
            #pragma unroll
            for (int mt = 0; mt < 2; mt++) {
                const int r = warpM * 32 + mt * 16 + qr;
                af[mt][0] = As[cur][r * AST + k0 + qc];
                af[mt][1] = As[cur][(r + 8) * AST + k0 + qc];
                af[mt][2] = As[cur][r * AST + k0 + qc + 4];
                af[mt][3] = As[cur][(r + 8) * AST + k0 + qc + 4];
            }
            #pragma unroll
            for (int nt = 0; nt < 8; nt++) {
                const int c = warpN * 64 + nt * 8 + qr;
                bf[nt][0] = Bs[cur][(k0 + qc) * BST + c];
                bf[nt][1] = Bs[cur][(k0 + qc + 4) * BST + c];
            }
            #pragma unroll
            for (int mt = 0; mt < 2; mt++)
                #pragma unroll
                for (int nt = 0; nt < 8; nt++)
                    mma_tf32(acc[mt][nt], af[mt], bf[nt][0], bf[nt][1]);
        }

        if (kt + 1 < NK) {
            const int nxt = cur ^ 1;
            uint4 u;
            u.x = f2tf(sa0.x); u.y = f2tf(sa0.y); u.z = f2tf(sa0.z); u.w = f2tf(sa0.w);
            *(uint4*)&As[nxt][ra * AST + ka] = u;
            u.x = f2tf(sa1.x); u.y = f2tf(sa1.y); u.z = f2tf(sa1.z); u.w = f2tf(sa1.w);
            *(uint4*)&As[nxt][(ra + 64) * AST + ka] = u;
            u.x = f2tf(sb0.x); u.y = f2tf(sb0.y); u.z = f2tf(sb0.z); u.w = f2tf(sb0.w);
            *(uint4*)&Bs[nxt][rb * BST + cb] = u;
            u.x = f2tf(sb1.x); u.y = f2tf(sb1.y); u.z = f2tf(sb1.z); u.w = f2tf(sb1.w);
            *(uint4*)&Bs[nxt][(rb + 8) * BST + cb] = u;
        }
        __syncthreads();
    }

    #pragma unroll
    for (int mt = 0; mt < 2; mt++) {
        const int r = row0 + warpM * 32 + mt * 16 + qr;
        #pragma unroll
        for (int nt = 0; nt < 8; nt++) {
            const int c = col0 + warpN * 64 + nt * 8 + 2 * qc;
            float v00 = acc[mt][nt][0] + bias[c];
            float v01 = acc[mt][nt][1] + bias[c + 1];
            float v10 = acc[mt][nt][2] + bias[c];
            float v11 = acc[mt][nt][3] + bias[c + 1];
            if (MODE == 0) {
                *(float2*)&C[(size_t)r * N + c]       = make_float2(v00, v01);
                *(float2*)&C[(size_t)(r + 8) * N + c] = make_float2(v10, v11);
            } else {
                #pragma unroll
                for (int e = 0; e < 4; e++) {
                    const int m = r + (e >> 1) * 8;
                    const int n = c + (e & 1);
                    const float val = (e == 0) ? v00 : (e == 1) ? v01 : (e == 2) ? v10 : v11;
                    const int sec = n >> 10;
                    const int cc  = n & 1023;
                    const int h   = cc >> 6;
                    const int d   = cc & 63;
                    const int b   = m >> 11;
                    const int t   = m & 2047;
                    const size_t dst = ((size_t)(b * N_HEADS + h) * SEQ + t) * HEAD_DIM + d;
                    if (sec == 0)      g_Q[dst] = val;
                    else if (sec == 1) g_K[dst] = val;
                    else               g_V[dst] = val;
                }
            }
        }
    }
}

// ---------------------------------------------------------------------------
// TF32 tensor-core causal flash attention.
// Block = 128 q rows (8 warps x 16 rows). K-tile = 64 keys.
// Q fragments persistent in registers; S via mma; online softmax in fragment
// layout; P through warp-private smem; PV mma accumulates into O fragments.
// ---------------------------------------------------------------------------
__global__ __launch_bounds__(256)
void flash_tc_kernel()
{
    constexpr int KST = 68;      // Ks/Vt row stride (floats)
    constexpr int PST = 68;      // Ps row stride

    extern __shared__ float smem[];
    float*    Ksm = smem;                       // [64][KST]  key-major (tf32 bits)
    float*    Vtm = smem + 64 * KST;            // [64][KST]  d-major  (tf32 bits)
    uint32_t* Psm = (uint32_t*)(smem + 2 * 64 * KST);  // [128][PST] tf32 P

    const int bh  = blockIdx.y;
    const int qx  = blockIdx.x;
    const int tid = threadIdx.x;
    const int wid = tid >> 5;
    const int lane = tid & 31;
    const int qr  = lane >> 2;
    const int qc  = lane & 3;

    const float* Qb = g_Q + (size_t)bh * SEQ * HEAD_DIM;
    const float* Kb = g_K + (size_t)bh * SEQ * HEAD_DIM;
    const float* Vb = g_V + (size_t)bh * SEQ * HEAD_DIM;

    const int rowbase = qx * 128 + wid * 16;    // first q row of this warp

    // Load Q fragments (persistent), scale folded: 0.125 * log2(e)
    const float qs = 0.125f * 1.4426950408889634f;
    uint32_t qf[8][4];
    #pragma unroll
    for (int kc = 0; kc < 8; kc++) {
        const float* r0 = Qb + (size_t)(rowbase + qr) * HEAD_DIM + kc * 8;
        const float* r1 = r0 + 8 * HEAD_DIM;
        qf[kc][0] = f2tf(r0[qc] * qs);
        qf[kc][1] = f2tf(r1[qc] * qs);
        qf[kc][2] = f2tf(r0[qc + 4] * qs);
        qf[kc][3] = f2tf(r1[qc + 4] * qs);
    }

    float oacc[8][4] = {};                      // O fragments [d-ntile][c]
    float m0 = -1e30f, m1 = -1e30f, l0 = 0.f, l1 = 0.f;

    const int nkt = 2 * (qx + 1);
    const int firstMasked = 2 * qx;

    const int ldkey = tid & 63;                 // coop-load key index
    const int lddq  = tid >> 6;                 // 0..3

    for (int kt = 0; kt < nkt; kt++) {
        const int kb = kt * 64;

        // ---- cooperative load: K (key-major) + V transposed (d-major), tf32 ----
        {
            const float* Kp = Kb + (size_t)(kb + ldkey) * HEAD_DIM;
            const float* Vp = Vb + (size_t)(kb + ldkey) * HEAD_DIM;
            #pragma unroll
            for (int i = 0; i < 4; i++) {
                const int d4 = lddq + i * 4;    // float4 index 0..15
                float4 kv = *(const float4*)(Kp + d4 * 4);
                uint4 ku;
                ku.x = f2tf(kv.x); ku.y = f2tf(kv.y); ku.z = f2tf(kv.z); ku.w = f2tf(kv.w);
                *(uint4*)&Ksm[ldkey * KST + d4 * 4] = ku;
                float4 vv = *(const float4*)(Vp + d4 * 4);
                ((uint32_t*)Vtm)[(d4 * 4 + 0) * KST + ldkey] = f2tf(vv.x);
                ((uint32_t*)Vtm)[(d4 * 4 + 1) * KST + ldkey] = f2tf(vv.y);
                ((uint32_t*)Vtm)[(d4 * 4 + 2) * KST + ldkey] = f2tf(vv.z);
                ((uint32_t*)Vtm)[(d4 * 4 + 3) * KST + ldkey] = f2tf(vv.w);
            }
        }
        __syncthreads();

        // ---- S = Q K^T ----
        float sa[8][4];
        #pragma unroll
        for (int nt = 0; nt < 8; nt++) {
            sa[nt][0] = 0.f; sa[nt][1] = 0.f; sa[nt][2] = 0.f; sa[nt][3] = 0.f;
        }
        const uint32_t* Ksu = (const uint32_t*)Ksm;
        #pragma unroll
        for (int kc = 0; kc < 8; kc++) {
            #pragma unroll
            for (int nt = 0; nt < 8; nt++) {
                const uint32_t b0 = Ksu[(nt * 8 + qr) * KST + kc * 8 + qc];
                const uint32_t b1 = Ksu[(nt * 8 + qr) * KST + kc * 8 + qc + 4];
                mma_tf32(sa[nt], qf[kc], b0, b1);
            }
        }

        // ---- causal mask (only on diagonal tiles) ----
        if (kt >= firstMasked) {
            const int r0g = rowbase + qr;
            const int r1g = r0g + 8;
            #pragma unroll
            for (int nt = 0; nt < 8; nt++) {
                const int cg = kb + nt * 8 + 2 * qc;
                if (cg     > r0g) sa[nt][0] = -1e30f;
                if (cg + 1 > r0g) sa[nt][1] = -1e30f;
                if (cg     > r1g) sa[nt][2] = -1e30f;
                if (cg + 1 > r1g) sa[nt][3] = -1e30f;
            }
        }

        // ---- online softmax (log2 domain) ----
        float t0 = -1e30f, t1 = -1e30f;
        #pragma unroll
        for (int nt = 0; nt < 8; nt++) {
            t0 = fmaxf(t0, fmaxf(sa[nt][0], sa[nt][1]));
            t1 = fmaxf(t1, fmaxf(sa[nt][2], sa[nt][3]));
        }
        t0 = fmaxf(t0, __shfl_xor_sync(0xffffffffu, t0, 1));
        t0 = fmaxf(t0, __shfl_xor_sync(0xffffffffu, t0, 2));
        t1 = fmaxf(t1, __shfl_xor_sync(0xffffffffu, t1, 1));
        t1 = fmaxf(t1, __shfl_xor_sync(0xffffffffu, t1, 2));

        const float mn0 = fmaxf(m0, t0);
        const float mn1 = fmaxf(m1, t1);
        const float c0 = ex2(m0 - mn0);
        const float c1 = ex2(m1 - mn1);
        l0 *= c0; l1 *= c1;
        #pragma unroll
        for (int nt = 0; nt < 8; nt++) {
            oacc[nt][0] *= c0; oacc[nt][1] *= c0;
            oacc[nt][2] *= c1; oacc[nt][3] *= c1;
        }

        float rs0 = 0.f, rs1 = 0.f;
        uint32_t* Pw0 = Psm + (size_t)(wid * 16 + qr) * PST;
        uint32_t* Pw1 = Pw0 + 8 * PST;
        #pragma unroll
        for (int nt = 0; nt < 8; nt++) {
            const float p00 = ex2(sa[nt][0] - mn0);
            const float p01 = ex2(sa[nt][1] - mn0);
            const float p10 = ex2(sa[nt][2] - mn1);
            const float p11 = ex2(sa[nt][3] - mn1);
            rs0 += p00 + p01;
            rs1 += p10 + p11;
            uint2 u0 = make_uint2(f2tf(p00), f2tf(p01));
            uint2 u1 = make_uint2(f2tf(p10), f2tf(p11));
            *(uint2*)&Pw0[nt * 8 + 2 * qc] = u0;
            *(uint2*)&Pw1[nt * 8 + 2 * qc] = u1;
        }
        rs0 += __shfl_xor_sync(0xffffffffu, rs0, 1);
        rs0 += __shfl_xor_sync(0xffffffffu, rs0, 2);
        rs1 += __shfl_xor_sync(0xffffffffu, rs1, 1);
        rs1 += __shfl_xor_sync(0xffffffffu, rs1, 2);
        l0 += rs0; l1 += rs1;
        m0 = mn0; m1 = mn1;

        __syncwarp();

        // ---- O += P V ----
        const uint32_t* Vtu = (const uint32_t*)Vtm;
        const uint32_t* Pr  = Psm + (size_t)(wid * 16 + qr) * PST;
        #pragma unroll
        for (int kc = 0; kc < 8; kc++) {
            uint32_t pa[4];
            pa[0] = Pr[kc * 8 + qc];
            pa[1] = Pr[8 * PST + kc * 8 + qc];
            pa[2] = Pr[kc * 8 + qc + 4];
            pa[3] = Pr[8 * PST + kc * 8 + qc + 4];
            #pragma unroll
            for (int nt = 0; nt < 8; nt++) {
                const uint32_t b0 = Vtu[(nt * 8 + qr) * KST + kc * 8 + qc];
                const uint32_t b1 = Vtu[(nt * 8 + qr) * KST + kc * 8 + qc + 4];
                mma_tf32(oacc[nt], pa, b0, b1);
            }
        }

        __syncthreads();
    }

    // ---- epilogue: normalize, write g_AO [B*T, C] ----
    const int b = bh >> 4;
    const int h = bh & 15;
    const float inv0 = 1.f / l0;
    const float inv1 = 1.f / l1;
    const int t0g = rowbase + qr;
    float* o0 = g_AO + ((size_t)(b * SEQ + t0g)) * D_MODEL + h * HEAD_DIM;
    float* o1 = o0 + 8 * D_MODEL;
    #pragma unroll
    for (int nt = 0; nt < 8; nt++) {
        *(float2*)&o0[nt * 8 + 2 * qc] = make_float2(oacc[nt][0] * inv0, oacc[nt][1] * inv0);
        *(float2*)&o1[nt * 8 + 2 * qc] = make_float2(oacc[nt][2] * inv1, oacc[nt][3] * inv1);
    }
}

// ---------------------------------------------------------------------------
extern "C" void kernel_launch(void* const* d_in, const int* in_sizes, int n_in,
                              void* d_out, int out_size)
{
    const float* x     = (const float*)d_in[0];
    const float* W_qkv = (const float*)d_in[1];
    const float* b_qkv = (const float*)d_in[2];
    const float* W_out = (const float*)d_in[3];
    const float* b_out = (const float*)d_in[4];
    float* out = (float*)d_out;

    const int flash_smem = (2 * 64 * 68 + 128 * 68) * 4;   // 69632 B
    cudaFuncSetAttribute(flash_tc_kernel,
                         cudaFuncAttributeMaxDynamicSharedMemorySize, flash_smem);

    // 1) QKV projection + scatter to [B,H,T,Dh]
    {
        dim3 grid(QKV_N / 128, MROWS / 128);   // (24, 64)
        tgemm_kernel<1><<<grid, 256>>>(x, W_qkv, b_qkv, nullptr,
                                       MROWS, QKV_N, D_MODEL);
    }
    // 2) Causal flash attention (tensor cores) -> g_AO [B*T, C]
    {
        dim3 grid(SEQ / 128, BATCH * N_HEADS); // (16, 64)
        flash_tc_kernel<<<grid, 256, flash_smem>>>();
    }
    // 3) Output projection -> d_out
    {
        dim3 grid(D_MODEL / 128, MROWS / 128); // (8, 64)
        tgemm_kernel<0><<<grid, 256>>>(nullptr, W_out, b_out, out,
                                       MROWS, D_MODEL, D_MODEL);
    }
}

// round 5
// speedup vs baseline: 3.1910x; 1.0107x over previous
#include <cuda_runtime.h>
#include <math.h>
#include <stdint.h>

#define D_MODEL 1024
#define N_HEADS 16
#define HEAD_DIM 64
#define BATCH 4
#define SEQ 2048
#define MROWS (BATCH * SEQ)          // 8192
#define QKV_N (3 * D_MODEL)          // 3072

// softmax scale folded into K at QKV epilogue: 1/sqrt(64) * log2(e)
#define KSCALE 0.18033688011111793f

// ---------------- scratch (__device__ globals; allocation-free rule) -------
// all tf32-bit payloads stored as uint32
__device__ __align__(16) uint32_t g_Q[BATCH * N_HEADS * SEQ * HEAD_DIM];
__device__ __align__(16) uint32_t g_K[BATCH * N_HEADS * SEQ * HEAD_DIM];
__device__ __align__(16) uint32_t g_V[BATCH * N_HEADS * SEQ * HEAD_DIM];
__device__ __align__(16) uint32_t g_AO[MROWS * D_MODEL];
__device__ __align__(16) uint32_t g_x32[MROWS * D_MODEL];
__device__ __align__(16) uint32_t g_w1[D_MODEL * QKV_N];     // [K][N]
__device__ __align__(16) uint32_t g_w2[D_MODEL * D_MODEL];   // [K][N]

// ---------------- helpers ---------------------------------------------------
__device__ __forceinline__ uint32_t smem_u32(const void* p) {
    uint32_t a;
    asm("{ .reg .u64 t; cvta.to.shared.u64 t, %1; cvt.u32.u64 %0, t; }"
        : "=r"(a) : "l"(p));
    return a;
}
__device__ __forceinline__ float ex2(float x) {
    float r; asm("ex2.approx.f32 %0, %1;" : "=f"(r) : "f"(x)); return r;
}
__device__ __forceinline__ uint32_t f2tf(float f) {
    uint32_t u; asm("cvt.rna.tf32.f32 %0, %1;" : "=r"(u) : "f"(f)); return u;
}
__device__ __forceinline__ void mma_tf32(float* d, const uint32_t* a,
                                         uint32_t b0, uint32_t b1) {
    asm volatile(
        "mma.sync.aligned.m16n8k8.row.col.f32.tf32.tf32.f32 "
        "{%0,%1,%2,%3}, {%4,%5,%6,%7}, {%8,%9}, {%0,%1,%2,%3};\n"
        : "+f"(d[0]), "+f"(d[1]), "+f"(d[2]), "+f"(d[3])
        : "r"(a[0]), "r"(a[1]), "r"(a[2]), "r"(a[3]), "r"(b0), "r"(b1));
}
#define CP16(dst, src) \
    asm volatile("cp.async.cg.shared.global [%0], [%1], 16;" :: "r"(dst), "l"(src))
#define CP_COMMIT() asm volatile("cp.async.commit_group;")
#define CP_WAIT(n)  asm volatile("cp.async.wait_group %0;" :: "n"(n))

// ---------------------------------------------------------------------------
// Elementwise fp32 -> tf32 bits
// ---------------------------------------------------------------------------
__global__ __launch_bounds__(256)
void cvt_tf32_kernel(const float4* __restrict__ src, uint4* __restrict__ dst, int n4)
{
    int i = blockIdx.x * blockDim.x + threadIdx.x;
    if (i >= n4) return;
    float4 v = src[i];
    uint4 u;
    u.x = f2tf(v.x); u.y = f2tf(v.y); u.z = f2tf(v.z); u.w = f2tf(v.w);
    dst[i] = u;
}

// ---------------------------------------------------------------------------
// TF32 tensor-core GEMM, pre-converted operands (uint32 tf32 bits).
// C[M,N] = A[M,K] @ B[K,N] + bias.  256x128 block tile, BK=16, 256 threads,
// 8 warps (4M x 2N), warp tile 64x64, cp.async double-buffered smem.
// MODE 0: write fp32 C.  MODE 1: scatter tf32 bits into g_Q/g_K(*KSCALE)/g_V.
// ---------------------------------------------------------------------------
template <int MODE>
__global__ __launch_bounds__(256, 1)
void tgemm2(const uint32_t* __restrict__ A, const uint32_t* __restrict__ Bm,
            const float* __restrict__ bias, float* __restrict__ C,
            int M, int N, int K)
{
    constexpr int AST = 20;            // As row stride (uint32)
    constexpr int BST = 136;           // Bs row stride
    constexpr int ABYTES = 256 * AST * 4;   // 20480
    constexpr int BBYTES = 16 * BST * 4;    // 8704

    extern __shared__ __align__(16) char smem[];
    uint32_t* Asm = (uint32_t*)smem;                    // [2][256*20]
    uint32_t* Bsm = (uint32_t*)(smem + 2 * ABYTES);     // [2][16*136]
    const uint32_t sA = smem_u32(smem);
    const uint32_t sB = sA + 2 * ABYTES;

    const int tid  = threadIdx.x;
    const int wid  = tid >> 5;
    const int lane = tid & 31;
    const int qr   = lane >> 2;
    const int qc   = lane & 3;
    const int wm   = wid >> 1;         // 0..3
    const int wn   = wid & 1;          // 0..1

    const int row0 = blockIdx.y * 256;
    const int col0 = blockIdx.x * 128;

    const int rb = tid >> 5;           // 0..7 (B rows rb, rb+8)
    const int cb = (tid & 31) * 4;

    const uint32_t* aS0 = A + (size_t)(row0 + tid) * K;
    const uint32_t* bS0 = Bm + (size_t)rb * N + col0 + cb;

    float acc[4][8][4] = {};
    const int NK = K / 16;

    // tile loader: A row `tid` (4x16B), B rows rb/rb+8 (2x16B)
    auto load_tile = [&](int kt, int buf) {
        const uint32_t aD = sA + buf * ABYTES + tid * (AST * 4);
        const uint32_t* aS = aS0 + kt * 16;
        CP16(aD,      aS);
        CP16(aD + 16, aS + 4);
        CP16(aD + 32, aS + 8);
        CP16(aD + 48, aS + 12);
        const uint32_t bD = sB + buf * BBYTES + rb * (BST * 4) + cb * 4;
        const uint32_t* bS = bS0 + (size_t)kt * 16 * N;
        CP16(bD, bS);
        CP16(bD + 8 * BST * 4, bS + (size_t)8 * N);
        CP_COMMIT();
    };

    load_tile(0, 0);

    for (int kt = 0; kt < NK; kt++) {
        const int cur = kt & 1;
        if (kt + 1 < NK) {
            load_tile(kt + 1, cur ^ 1);
            CP_WAIT(1);
        } else {
            CP_WAIT(0);
        }
        __syncthreads();

        const uint32_t* Ab = Asm + cur * (256 * AST);
        const uint32_t* Bb = Bsm + cur * (16 * BST);
        #pragma unroll
        for (int ks = 0; ks < 2; ks++) {
            const int k0 = ks * 8;
            uint32_t af[4][4], bf[8][2];
            #pragma unroll
            for (int mt = 0; mt < 4; mt++) {
                const int r = wm * 64 + mt * 16 + qr;
                af[mt][0] = Ab[r * AST + k0 + qc];
                af[mt][1] = Ab[(r + 8) * AST + k0 + qc];
                af[mt][2] = Ab[r * AST + k0 + qc + 4];
                af[mt][3] = Ab[(r + 8) * AST + k0 + qc + 4];
            }
            #pragma unroll
            for (int nt = 0; nt < 8; nt++) {
                const int c = wn * 64 + nt * 8 + qr;
                bf[nt][0] = Bb[(k0 + qc) * BST + c];
                bf[nt][1] = Bb[(k0 + qc + 4) * BST + c];
            }
            #pragma unroll
            for (int mt = 0; mt < 4; mt++)
                #pragma unroll
                for (int nt = 0; nt < 8; nt++)
                    mma_tf32(acc[mt][nt], af[mt], bf[nt][0], bf[nt][1]);
        }
        __syncthreads();
    }

    // epilogue
    #pragma unroll
    for (int mt = 0; mt < 4; mt++) {
        const int r = row0 + wm * 64 + mt * 16 + qr;
        #pragma unroll
        for (int nt = 0; nt < 8; nt++) {
            const int c = col0 + wn * 64 + nt * 8 + 2 * qc;
            const float bz0 = bias[c], bz1 = bias[c + 1];
            const float v00 = acc[mt][nt][0] + bz0;
            const float v01 = acc[mt][nt][1] + bz1;
            const float v10 = acc[mt][nt][2] + bz0;
            const float v11 = acc[mt][nt][3] + bz1;
            if (MODE == 0) {
                *(float2*)&C[(size_t)r * N + c]       = make_float2(v00, v01);
                *(float2*)&C[(size_t)(r + 8) * N + c] = make_float2(v10, v11);
            } else {
                const int sec = c >> 10, cc = c & 1023;
                const int h = cc >> 6, d = cc & 63;
                const int b = r >> 11, t = r & 2047;
                const float sc = (sec == 1) ? KSCALE : 1.0f;
                uint32_t* dst = (sec == 0 ? g_Q : sec == 1 ? g_K : g_V);
                const size_t off = ((size_t)(b * N_HEADS + h) * SEQ + t) * HEAD_DIM + d;
                *(uint2*)&dst[off] = make_uint2(f2tf(v00 * sc), f2tf(v01 * sc));
                *(uint2*)&dst[off + 8 * HEAD_DIM] =
                    make_uint2(f2tf(v10 * sc), f2tf(v11 * sc));
            }
        }
    }
}

// ---------------------------------------------------------------------------
// TF32 tensor-core causal flash attention.
// K tile key-major stride 68 (S B-frags: bank=4qr+qc, conflict-free).
// V tile key-major stride 72 (PV B-frags: bank=8qc+qr, conflict-free).
// Both tiles pure cp.async copies (Q/K/V already tf32 bits; scale in K).
// ---------------------------------------------------------------------------
__global__ __launch_bounds__(256)
void flash_tc_kernel()
{
    constexpr int KST = 68;
    constexpr int VST = 72;
    constexpr int PST = 68;
    constexpr int KB  = 64 * KST * 4;   // 17408
    constexpr int VB  = 64 * VST * 4;   // 18432

    extern __shared__ __align__(16) char smemc[];
    uint32_t* Ksm = (uint32_t*)smemc;
    uint32_t* Vsm = (uint32_t*)(smemc + KB);
    uint32_t* Psm = (uint32_t*)(smemc + KB + VB);
    const uint32_t sK = smem_u32(smemc);
    const uint32_t sV = sK + KB;

    const int bh   = blockIdx.y;
    const int qx   = blockIdx.x;
    const int tid  = threadIdx.x;
    const int wid  = tid >> 5;
    const int lane = tid & 31;
    const int qr   = lane >> 2;
    const int qc   = lane & 3;

    const uint32_t* Qb = g_Q + (size_t)bh * SEQ * HEAD_DIM;
    const uint32_t* Kb = g_K + (size_t)bh * SEQ * HEAD_DIM;
    const uint32_t* Vb = g_V + (size_t)bh * SEQ * HEAD_DIM;

    const int rowbase = qx * 128 + wid * 16;

    // persistent Q fragments (raw tf32 bits; softmax scale folded into K)
    uint32_t qf[8][4];
    {
        const uint32_t* r0 = Qb + (size_t)(rowbase + qr) * HEAD_DIM;
        const uint32_t* r1 = r0 + 8 * HEAD_DIM;
        #pragma unroll
        for (int kc = 0; kc < 8; kc++) {
            qf[kc][0] = r0[kc * 8 + qc];
            qf[kc][1] = r1[kc * 8 + qc];
            qf[kc][2] = r0[kc * 8 + qc + 4];
            qf[kc][3] = r1[kc * 8 + qc + 4];
        }
    }

    float oacc[8][4] = {};
    float m0 = -1e30f, m1 = -1e30f, l0 = 0.f, l1 = 0.f;

    const int nkt = 2 * (qx + 1);
    const int firstMasked = 2 * qx;

    const int ldkey = tid >> 2;          // 0..63
    const int ldch  = tid & 3;           // chunk base (of 16 16B-chunks/row)

    for (int kt = 0; kt < nkt; kt++) {
        const int kb = kt * 64;

        // ---- cp.async tile load: K and V, key-major ----
        {
            const uint32_t kD = sK + ldkey * (KST * 4) + ldch * 16;
            const uint32_t vD = sV + ldkey * (VST * 4) + ldch * 16;
            const uint32_t* kS = Kb + (size_t)(kb + ldkey) * HEAD_DIM + ldch * 4;
            const uint32_t* vS = Vb + (size_t)(kb + ldkey) * HEAD_DIM + ldch * 4;
            #pragma unroll
            for (int i = 0; i < 4; i++) {
                CP16(kD + i * 64, kS + i * 16);
                CP16(vD + i * 64, vS + i * 16);
            }
            CP_COMMIT();
            CP_WAIT(0);
        }
        __syncthreads();

        // ---- S = Q K^T ----
        float sa[8][4];
        #pragma unroll
        for (int nt = 0; nt < 8; nt++) {
            sa[nt][0] = 0.f; sa[nt][1] = 0.f; sa[nt][2] = 0.f; sa[nt][3] = 0.f;
        }
        #pragma unroll
        for (int kc = 0; kc < 8; kc++) {
            #pragma unroll
            for (int nt = 0; nt < 8; nt++) {
                const uint32_t b0 = Ksm[(nt * 8 + qr) * KST + kc * 8 + qc];
                const uint32_t b1 = Ksm[(nt * 8 + qr) * KST + kc * 8 + qc + 4];
                mma_tf32(sa[nt], qf[kc], b0, b1);
            }
        }

        // ---- causal mask (diagonal tiles only) ----
        if (kt >= firstMasked) {
            const int r0g = rowbase + qr;
            const int r1g = r0g + 8;
            #pragma unroll
            for (int nt = 0; nt < 8; nt++) {
                const int cg = kb + nt * 8 + 2 * qc;
                if (cg     > r0g) sa[nt][0] = -1e30f;
                if (cg + 1 > r0g) sa[nt][1] = -1e30f;
                if (cg     > r1g) sa[nt][2] = -1e30f;
                if (cg + 1 > r1g) sa[nt][3] = -1e30f;
            }
        }

        // ---- online softmax (log2 domain) ----
        float t0 = -1e30f, t1 = -1e30f;
        #pragma unroll
        for (int nt = 0; nt < 8; nt++) {
            t0 = fmaxf(t0, fmaxf(sa[nt][0], sa[nt][1]));
            t1 = fmaxf(t1, fmaxf(sa[nt][2], sa[nt][3]));
        }
        t0 = fmaxf(t0, __shfl_xor_sync(0xffffffffu, t0, 1));
        t0 = fmaxf(t0, __shfl_xor_sync(0xffffffffu, t0, 2));
        t1 = fmaxf(t1, __shfl_xor_sync(0xffffffffu, t1, 1));
        t1 = fmaxf(t1, __shfl_xor_sync(0xffffffffu, t1, 2));

        const float mn0 = fmaxf(m0, t0);
        const float mn1 = fmaxf(m1, t1);
        const float c0 = ex2(m0 - mn0);
        const float c1 = ex2(m1 - mn1);
        l0 *= c0; l1 *= c1;
        #pragma unroll
        for (int nt = 0; nt < 8; nt++) {
            oacc[nt][0] *= c0; oacc[nt][1] *= c0;
            oacc[nt][2] *= c1; oacc[nt][3] *= c1;
        }

        float rs0 = 0.f, rs1 = 0.f;
        uint32_t* Pw0 = Psm + (size_t)(wid * 16 + qr) * PST;
        uint32_t* Pw1 = Pw0 + 8 * PST;
        #pragma unroll
        for (int nt = 0; nt < 8; nt++) {
            const float p00 = ex2(sa[nt][0] - mn0);
            const float p01 = ex2(sa[nt][1] - mn0);
            const float p10 = ex2(sa[nt][2] - mn1);
            const float p11 = ex2(sa[nt][3] - mn1);
            rs0 += p00 + p01;
            rs1 += p10 + p11;
            *(uint2*)&Pw0[nt * 8 + 2 * qc] = make_uint2(f2tf(p00), f2tf(p01));
            *(uint2*)&Pw1[nt * 8 + 2 * qc] = make_uint2(f2tf(p10), f2tf(p11));
        }
        rs0 += __shfl_xor_sync(0xffffffffu, rs0, 1);
        rs0 += __shfl_xor_sync(0xffffffffu, rs0, 2);
        rs1 += __shfl_xor_sync(0xffffffffu, rs1, 1);
        rs1 += __shfl_xor_sync(0xffffffffu, rs1, 2);
        l0 += rs0; l1 += rs1;
        m0 = mn0; m1 = mn1;

        __syncwarp();

        // ---- O += P V ----
        const uint32_t* Pr = Psm + (size_t)(wid * 16 + qr) * PST;
        #pragma unroll
        for (int kc = 0; kc < 8; kc++) {
            uint32_t pa[4];
            pa[0] = Pr[kc * 8 + qc];
            pa[1] = Pr[8 * PST + kc * 8 + qc];
            pa[2] = Pr[kc * 8 + qc + 4];
            pa[3] = Pr[8 * PST + kc * 8 + qc + 4];
            #pragma unroll
            for (int nt = 0; nt < 8; nt++) {
                const uint32_t b0 = Vsm[(kc * 8 + qc) * VST + nt * 8 + qr];
                const uint32_t b1 = Vsm[(kc * 8 + qc + 4) * VST + nt * 8 + qr];
                mma_tf32(oacc[nt], pa, b0, b1);
            }
        }

        __syncthreads();
    }

    // ---- epilogue: normalize, write tf32 bits to g_AO [B*T][C] ----
    const int b = bh >> 4;
    const int h = bh & 15;
    const float inv0 = 1.f / l0;
    const float inv1 = 1.f / l1;
    const int t0g = rowbase + qr;
    uint32_t* o0 = g_AO + ((size_t)(b * SEQ + t0g)) * D_MODEL + h * HEAD_DIM;
    uint32_t* o1 = o0 + 8 * D_MODEL;
    #pragma unroll
    for (int nt = 0; nt < 8; nt++) {
        *(uint2*)&o0[nt * 8 + 2 * qc] =
            make_uint2(f2tf(oacc[nt][0] * inv0), f2tf(oacc[nt][1] * inv0));
        *(uint2*)&o1[nt * 8 + 2 * qc] =
            make_uint2(f2tf(oacc[nt][2] * inv1), f2tf(oacc[nt][3] * inv1));
    }
}

// ---------------------------------------------------------------------------
extern "C" void kernel_launch(void* const* d_in, const int* in_sizes, int n_in,
                              void* d_out, int out_size)
{
    const float* x     = (const float*)d_in[0];
    const float* W_qkv = (const float*)d_in[1];
    const float* b_qkv = (const float*)d_in[2];
    const float* W_out = (const float*)d_in[3];
    const float* b_out = (const float*)d_in[4];
    float* out = (float*)d_out;

    const int gemm_smem  = 2 * 20480 + 2 * 8704;                       // 58368
    const int flash_smem = (64 * 68 + 64 * 72 + 128 * 68) * 4;         // 70656
    cudaFuncSetAttribute(tgemm2<0>, cudaFuncAttributeMaxDynamicSharedMemorySize, gemm_smem);
    cudaFuncSetAttribute(tgemm2<1>, cudaFuncAttributeMaxDynamicSharedMemorySize, gemm_smem);
    cudaFuncSetAttribute(flash_tc_kernel, cudaFuncAttributeMaxDynamicSharedMemorySize, flash_smem);

    uint32_t *x32, *w1, *w2, *ao;
    cudaGetSymbolAddress((void**)&x32, g_x32);
    cudaGetSymbolAddress((void**)&w1,  g_w1);
    cudaGetSymbolAddress((void**)&w2,  g_w2);
    cudaGetSymbolAddress((void**)&ao,  g_AO);

    // 0) pre-convert fp32 -> tf32 bits
    {
        int n4 = MROWS * D_MODEL / 4;
        cvt_tf32_kernel<<<(n4 + 255) / 256, 256>>>((const float4*)x, (uint4*)x32, n4);
        n4 = D_MODEL * QKV_N / 4;
        cvt_tf32_kernel<<<(n4 + 255) / 256, 256>>>((const float4*)W_qkv, (uint4*)w1, n4);
        n4 = D_MODEL * D_MODEL / 4;
        cvt_tf32_kernel<<<(n4 + 255) / 256, 256>>>((const float4*)W_out, (uint4*)w2, n4);
    }
    // 1) QKV projection -> g_Q / g_K (scaled) / g_V (tf32 bits)
    {
        dim3 grid(QKV_N / 128, MROWS / 256);    // (24, 32)
        tgemm2<1><<<grid, 256, gemm_smem>>>(x32, w1, b_qkv, nullptr,
                                            MROWS, QKV_N, D_MODEL);
    }
    // 2) causal flash attention -> g_AO (tf32 bits)
    {
        dim3 grid(SEQ / 128, BATCH * N_HEADS);  // (16, 64)
        flash_tc_kernel<<<grid, 256, flash_smem>>>();
    }
    // 3) output projection -> d_out (fp32)
    {
        dim3 grid(D_MODEL / 128, MROWS / 256);  // (8, 32)
        tgemm2<0><<<grid, 256, gemm_smem>>>(ao, w2, b_out, out,
                                            MROWS, D_MODEL, D_MODEL);
    }
}

// round 6
// speedup vs baseline: 3.3455x; 1.0484x over previous
#include <cuda_runtime.h>
#include <math.h>
#include <stdint.h>

#define D_MODEL 1024
#define N_HEADS 16
#define HEAD_DIM 64
#define BATCH 4
#define SEQ 2048
#define MROWS (BATCH * SEQ)          // 8192
#define QKV_N (3 * D_MODEL)          // 3072

// softmax scale folded into K at QKV epilogue: 1/sqrt(64) * log2(e)
#define KSCALE 0.18033688011111793f

// ---------------- scratch (__device__ globals) ------------------------------
__device__ __align__(16) uint32_t g_Q[BATCH * N_HEADS * SEQ * HEAD_DIM];
__device__ __align__(16) uint32_t g_K[BATCH * N_HEADS * SEQ * HEAD_DIM];
__device__ __align__(16) uint32_t g_V[BATCH * N_HEADS * SEQ * HEAD_DIM];
__device__ __align__(16) uint32_t g_AO[MROWS * D_MODEL];
__device__ __align__(16) uint32_t g_x32[MROWS * D_MODEL];
__device__ __align__(16) uint32_t g_w1t[QKV_N * D_MODEL];    // [N][K] tf32
__device__ __align__(16) uint32_t g_w2t[D_MODEL * D_MODEL];  // [N][K] tf32

// ---------------- helpers ----------------------------------------------------
__device__ __forceinline__ uint32_t smem_u32(const void* p) {
    uint32_t a;
    asm("{ .reg .u64 t; cvta.to.shared.u64 t, %1; cvt.u32.u64 %0, t; }"
        : "=r"(a) : "l"(p));
    return a;
}
__device__ __forceinline__ float ex2(float x) {
    float r; asm("ex2.approx.f32 %0, %1;" : "=f"(r) : "f"(x)); return r;
}
__device__ __forceinline__ uint32_t f2tf(float f) {
    uint32_t u; asm("cvt.rna.tf32.f32 %0, %1;" : "=r"(u) : "f"(f)); return u;
}
__device__ __forceinline__ void mma_tf32(float* d, const uint32_t* a,
                                         uint32_t b0, uint32_t b1) {
    asm volatile(
        "mma.sync.aligned.m16n8k8.row.col.f32.tf32.tf32.f32 "
        "{%0,%1,%2,%3}, {%4,%5,%6,%7}, {%8,%9}, {%0,%1,%2,%3};\n"
        : "+f"(d[0]), "+f"(d[1]), "+f"(d[2]), "+f"(d[3])
        : "r"(a[0]), "r"(a[1]), "r"(a[2]), "r"(a[3]), "r"(b0), "r"(b1));
}
#define LDSM4(r0, r1, r2, r3, addr) \
    asm volatile("ldmatrix.sync.aligned.m8n8.x4.shared.b16 {%0,%1,%2,%3}, [%4];" \
                 : "=r"(r0), "=r"(r1), "=r"(r2), "=r"(r3) : "r"(addr))
#define CP16(dst, src) \
    asm volatile("cp.async.cg.shared.global [%0], [%1], 16;" :: "r"(dst), "l"(src))
#define CP_COMMIT() asm volatile("cp.async.commit_group;")
#define CP_WAIT(n)  asm volatile("cp.async.wait_group %0;" :: "n"(n))

// ---------------------------------------------------------------------------
// Elementwise fp32 -> tf32 bits
// ---------------------------------------------------------------------------
__global__ __launch_bounds__(256)
void cvt_tf32_kernel(const float4* __restrict__ src, uint4* __restrict__ dst, int n4)
{
    int i = blockIdx.x * blockDim.x + threadIdx.x;
    if (i >= n4) return;
    float4 v = src[i];
    uint4 u;
    u.x = f2tf(v.x); u.y = f2tf(v.y); u.z = f2tf(v.z); u.w = f2tf(v.w);
    dst[i] = u;
}

// Transpose + convert: W[K][N] fp32 -> T[N][K] tf32 bits
__global__ __launch_bounds__(256)
void cvt_transpose_tf32(const float* __restrict__ W, uint32_t* __restrict__ T,
                        int K, int N)
{
    __shared__ float tile[32][33];
    const int k0 = blockIdx.y * 32, n0 = blockIdx.x * 32;
    const int tx = threadIdx.x, ty = threadIdx.y;     // 32 x 8
    #pragma unroll
    for (int i = 0; i < 32; i += 8)
        tile[ty + i][tx] = W[(size_t)(k0 + ty + i) * N + n0 + tx];
    __syncthreads();
    #pragma unroll
    for (int i = 0; i < 32; i += 8)
        T[(size_t)(n0 + ty + i) * K + k0 + tx] = f2tf(tile[tx][ty + i]);
}

// ---------------------------------------------------------------------------
// TF32 GEMM: C[M,N] = A[M,K] @ Bt[N,K]^T + bias.  128x128 tile, BK=16,
// 256 thr (8 warps, 4Mx2N, warp 32x64), cp.async double buffer, ldmatrix frags.
// MODE 0: fp32 C.  MODE 1: scatter tf32 bits into g_Q/g_K(*KSCALE)/g_V.
// ---------------------------------------------------------------------------
template <int MODE>
__global__ __launch_bounds__(256, 2)
void tgemm3(const uint32_t* __restrict__ A, const uint32_t* __restrict__ Bt,
            const float* __restrict__ bias, float* __restrict__ C,
            int M, int N, int K)
{
    constexpr int AST = 20;              // row stride (uint32), ldmatrix-conflict-free
    constexpr int TB  = 128 * AST;       // uint32 per operand buffer

    extern __shared__ __align__(16) uint32_t sm[];
    const uint32_t sA = smem_u32(sm);
    const uint32_t sB = sA + 2 * TB * 4;

    const int tid  = threadIdx.x;
    const int wid  = tid >> 5;
    const int lane = tid & 31;
    const int qr   = lane >> 2;
    const int qc   = lane & 3;
    const int wm   = wid >> 1;           // 0..3 (32 rows)
    const int wn   = wid & 1;            // 0..1 (64 cols)

    const int row0 = blockIdx.y * 128;
    const int col0 = blockIdx.x * 128;

    // cp.async coords: thread covers one half-row (8 k) of A and of Bt
    const int lr = tid >> 1, lh = (tid & 1) * 8;
    const uint32_t* aS0 = A  + (size_t)(row0 + lr) * K + lh;
    const uint32_t* bS0 = Bt + (size_t)(col0 + lr) * K + lh;
    const uint32_t aD0 = sA + (lr * AST + lh) * 4;
    const uint32_t bD0 = sB + (lr * AST + lh) * 4;

    // ldmatrix lane addressing
    const int a_row = wm * 32 + (lane & 7) + ((lane >> 3) & 1) * 8;
    const int a_col = (lane >> 4) * 4;
    const int b_row = wn * 64 + (lane >> 4) * 8 + (lane & 7);
    const int b_col = ((lane >> 3) & 1) * 4;

    float acc[2][8][4] = {};
    const int NK = K / 16;

    {   // prologue
        CP16(aD0, aS0); CP16(aD0 + 16, aS0 + 4);
        CP16(bD0, bS0); CP16(bD0 + 16, bS0 + 4);
        CP_COMMIT();
    }

    for (int kt = 0; kt < NK; kt++) {
        const int cur = kt & 1;
        if (kt + 1 < NK) {
            const uint32_t* as = aS0 + (kt + 1) * 16;
            const uint32_t* bs = bS0 + (kt + 1) * 16;
            const uint32_t ad = aD0 + (cur ^ 1) * TB * 4;
            const uint32_t bd = bD0 + (cur ^ 1) * TB * 4;
            CP16(ad, as); CP16(ad + 16, as + 4);
            CP16(bd, bs); CP16(bd + 16, bs + 4);
            CP_COMMIT();
            CP_WAIT(1);
        } else {
            CP_WAIT(0);
        }
        __syncthreads();

        const uint32_t ab = sA + cur * TB * 4;
        const uint32_t bb = sB + cur * TB * 4;
        #pragma unroll
        for (int ks = 0; ks < 2; ks++) {
            uint32_t af[2][4], bf[8][2];
            #pragma unroll
            for (int mt = 0; mt < 2; mt++)
                LDSM4(af[mt][0], af[mt][1], af[mt][2], af[mt][3],
                      ab + (((a_row + mt * 16) * AST) + ks * 8 + a_col) * 4);
            #pragma unroll
            for (int np = 0; np < 4; np++)
                LDSM4(bf[np * 2][0], bf[np * 2][1], bf[np * 2 + 1][0], bf[np * 2 + 1][1],
                      bb + (((b_row + np * 16) * AST) + ks * 8 + b_col) * 4);
            #pragma unroll
            for (int mt = 0; mt < 2; mt++)
                #pragma unroll
                for (int nt = 0; nt < 8; nt++)
                    mma_tf32(acc[mt][nt], af[mt], bf[nt][0], bf[nt][1]);
        }
        __syncthreads();
    }

    // epilogue
    #pragma unroll
    for (int mt = 0; mt < 2; mt++) {
        const int r = row0 + wm * 32 + mt * 16 + qr;
        #pragma unroll
        for (int nt = 0; nt < 8; nt++) {
            const int c = col0 + wn * 64 + nt * 8 + 2 * qc;
            const float bz0 = bias[c], bz1 = bias[c + 1];
            const float v00 = acc[mt][nt][0] + bz0;
            const float v01 = acc[mt][nt][1] + bz1;
            const float v10 = acc[mt][nt][2] + bz0;
            const float v11 = acc[mt][nt][3] + bz1;
            if (MODE == 0) {
                *(float2*)&C[(size_t)r * N + c]       = make_float2(v00, v01);
                *(float2*)&C[(size_t)(r + 8) * N + c] = make_float2(v10, v11);
            } else {
                const int sec = c >> 10, cc = c & 1023;
                const int h = cc >> 6, d = cc & 63;
                const int b = r >> 11, t = r & 2047;
                const float sc = (sec == 1) ? KSCALE : 1.0f;
                uint32_t* dst = (sec == 0 ? g_Q : sec == 1 ? g_K : g_V);
                const size_t off = ((size_t)(b * N_HEADS + h) * SEQ + t) * HEAD_DIM + d;
                *(uint2*)&dst[off] = make_uint2(f2tf(v00 * sc), f2tf(v01 * sc));
                *(uint2*)&dst[off + 8 * HEAD_DIM] =
                    make_uint2(f2tf(v10 * sc), f2tf(v11 * sc));
            }
        }
    }
}

// ---------------------------------------------------------------------------
// TF32 flash attention, causal.  128 q rows (8 warps x 16), K-tile 64.
// K [key][d] (cp.async), V transposed to [d][key] at load, P [row][k];
// all fragments via ldmatrix.x4.
// ---------------------------------------------------------------------------
__global__ __launch_bounds__(256)
void flash_tc_kernel()
{
    constexpr int KST = 68;     // K rows (key-major)
    constexpr int VST = 68;     // Vt rows (d-major)
    constexpr int PST = 68;
    constexpr int KB  = 64 * KST * 4;   // 17408
    constexpr int VB  = 64 * VST * 4;

    extern __shared__ __align__(16) char smemc[];
    uint32_t* Vsm = (uint32_t*)(smemc + KB);
    uint32_t* Psm = (uint32_t*)(smemc + KB + VB);
    const uint32_t sK = smem_u32(smemc);
    const uint32_t sV = sK + KB;
    const uint32_t sP = sV + VB;

    const int bh   = blockIdx.y;
    const int qx   = blockIdx.x;
    const int tid  = threadIdx.x;
    const int wid  = tid >> 5;
    const int lane = tid & 31;
    const int qr   = lane >> 2;
    const int qc   = lane & 3;

    const uint32_t* Qb = g_Q + (size_t)bh * SEQ * HEAD_DIM;
    const uint32_t* Kb = g_K + (size_t)bh * SEQ * HEAD_DIM;
    const uint32_t* Vb = g_V + (size_t)bh * SEQ * HEAD_DIM;

    const int rowbase = qx * 128 + wid * 16;

    // persistent Q fragments (raw tf32 bits; scale folded into K)
    uint32_t qf[8][4];
    {
        const uint32_t* r0 = Qb + (size_t)(rowbase + qr) * HEAD_DIM;
        const uint32_t* r1 = r0 + 8 * HEAD_DIM;
        #pragma unroll
        for (int kc = 0; kc < 8; kc++) {
            qf[kc][0] = r0[kc * 8 + qc];
            qf[kc][1] = r1[kc * 8 + qc];
            qf[kc][2] = r0[kc * 8 + qc + 4];
            qf[kc][3] = r1[kc * 8 + qc + 4];
        }
    }

    float oacc[8][4] = {};
    float m0 = -1e30f, m1 = -1e30f, l0 = 0.f, l1 = 0.f;

    const int nkt = 2 * (qx + 1);
    const int firstMasked = 2 * qx;

    // K cp.async coords
    const int ldkey = tid >> 2;
    const int ldch  = tid & 3;
    // V transpose coords
    const int vkey = tid & 63;
    const int vdq  = tid >> 6;           // 0..3

    // ldmatrix lane addressing (B-pattern on K/Vt; A-pattern on P)
    const int nb_row = (lane >> 4) * 8 + (lane & 7);
    const int nb_col = ((lane >> 3) & 1) * 4;
    const int p_row  = wid * 16 + (lane & 7) + ((lane >> 3) & 1) * 8;
    const int p_col  = (lane >> 4) * 4;

    for (int kt = 0; kt < nkt; kt++) {
        const int kb = kt * 64;

        // K tile via cp.async
        {
            const uint32_t kD = sK + ldkey * (KST * 4) + ldch * 16;
            const uint32_t* kS = Kb + (size_t)(kb + ldkey) * HEAD_DIM + ldch * 4;
            #pragma unroll
            for (int i = 0; i < 4; i++) CP16(kD + i * 64, kS + i * 16);
            CP_COMMIT();
        }
        // V tile transposed: [d][key]
        {
            const uint32_t* vS = Vb + (size_t)(kb + vkey) * HEAD_DIM;
            #pragma unroll
            for (int i = 0; i < 4; i++) {
                uint4 v = *(const uint4*)(vS + (vdq + i * 4) * 4);
                const int d0 = (vdq + i * 4) * 4;
                Vsm[(d0 + 0) * VST + vkey] = v.x;
                Vsm[(d0 + 1) * VST + vkey] = v.y;
                Vsm[(d0 + 2) * VST + vkey] = v.z;
                Vsm[(d0 + 3) * VST + vkey] = v.w;
            }
        }
        CP_WAIT(0);
        __syncthreads();

        // ---- S = Q K^T (K ldmatrix) ----
        float sa[8][4];
        #pragma unroll
        for (int nt = 0; nt < 8; nt++) {
            sa[nt][0] = 0.f; sa[nt][1] = 0.f; sa[nt][2] = 0.f; sa[nt][3] = 0.f;
        }
        #pragma unroll
        for (int kc = 0; kc < 8; kc++) {
            #pragma unroll
            for (int np = 0; np < 4; np++) {
                uint32_t r0, r1, r2, r3;
                LDSM4(r0, r1, r2, r3,
                      sK + (((np * 16 + nb_row) * KST) + kc * 8 + nb_col) * 4);
                mma_tf32(sa[np * 2],     qf[kc], r0, r1);
                mma_tf32(sa[np * 2 + 1], qf[kc], r2, r3);
            }
        }

        // ---- causal mask (diagonal tiles only) ----
        if (kt >= firstMasked) {
            const int r0g = rowbase + qr;
            const int r1g = r0g + 8;
            #pragma unroll
            for (int nt = 0; nt < 8; nt++) {
                const int cg = kb + nt * 8 + 2 * qc;
                if (cg     > r0g) sa[nt][0] = -1e30f;
                if (cg + 1 > r0g) sa[nt][1] = -1e30f;
                if (cg     > r1g) sa[nt][2] = -1e30f;
                if (cg + 1 > r1g) sa[nt][3] = -1e30f;
            }
        }

        // ---- online softmax (log2 domain) ----
        float t0 = -1e30f, t1 = -1e30f;
        #pragma unroll
        for (int nt = 0; nt < 8; nt++) {
            t0 = fmaxf(t0, fmaxf(sa[nt][0], sa[nt][1]));
            t1 = fmaxf(t1, fmaxf(sa[nt][2], sa[nt][3]));
        }
        t0 = fmaxf(t0, __shfl_xor_sync(0xffffffffu, t0, 1));
        t0 = fmaxf(t0, __shfl_xor_sync(0xffffffffu, t0, 2));
        t1 = fmaxf(t1, __shfl_xor_sync(0xffffffffu, t1, 1));
        t1 = fmaxf(t1, __shfl_xor_sync(0xffffffffu, t1, 2));

        const float mn0 = fmaxf(m0, t0);
        const float mn1 = fmaxf(m1, t1);
        const float c0 = ex2(m0 - mn0);
        const float c1 = ex2(m1 - mn1);
        l0 *= c0; l1 *= c1;
        #pragma unroll
        for (int nt = 0; nt < 8; nt++) {
            oacc[nt][0] *= c0; oacc[nt][1] *= c0;
            oacc[nt][2] *= c1; oacc[nt][3] *= c1;
        }

        float rs0 = 0.f, rs1 = 0.f;
        uint32_t* Pw0 = Psm + (size_t)(wid * 16 + qr) * PST;
        uint32_t* Pw1 = Pw0 + 8 * PST;
        #pragma unroll
        for (int nt = 0; nt < 8; nt++) {
            const float p00 = ex2(sa[nt][0] - mn0);
            const float p01 = ex2(sa[nt][1] - mn0);
            const float p10 = ex2(sa[nt][2] - mn1);
            const float p11 = ex2(sa[nt][3] - mn1);
            rs0 += p00 + p01;
            rs1 += p10 + p11;
            *(uint2*)&Pw0[nt * 8 + 2 * qc] = make_uint2(f2tf(p00), f2tf(p01));
            *(uint2*)&Pw1[nt * 8 + 2 * qc] = make_uint2(f2tf(p10), f2tf(p11));
        }
        rs0 += __shfl_xor_sync(0xffffffffu, rs0, 1);
        rs0 += __shfl_xor_sync(0xffffffffu, rs0, 2);
        rs1 += __shfl_xor_sync(0xffffffffu, rs1, 1);
        rs1 += __shfl_xor_sync(0xffffffffu, rs1, 2);
        l0 += rs0; l1 += rs1;
        m0 = mn0; m1 = mn1;

        __syncwarp();

        // ---- O += P V  (P A-frags + Vt B-frags via ldmatrix) ----
        #pragma unroll
        for (int kc = 0; kc < 8; kc++) {
            uint32_t pa[4];
            LDSM4(pa[0], pa[1], pa[2], pa[3],
                  sP + ((p_row * PST) + kc * 8 + p_col) * 4);
            #pragma unroll
            for (int np = 0; np < 4; np++) {
                uint32_t r0, r1, r2, r3;
                LDSM4(r0, r1, r2, r3,
                      sV + (((np * 16 + nb_row) * VST) + kc * 8 + nb_col) * 4);
                mma_tf32(oacc[np * 2],     pa, r0, r1);
                mma_tf32(oacc[np * 2 + 1], pa, r2, r3);
            }
        }

        __syncthreads();
    }

    // ---- epilogue: normalize, write tf32 bits to g_AO [B*T][C] ----
    const int b = bh >> 4;
    const int h = bh & 15;
    const float inv0 = 1.f / l0;
    const float inv1 = 1.f / l1;
    const int t0g = rowbase + qr;
    uint32_t* o0 = g_AO + ((size_t)(b * SEQ + t0g)) * D_MODEL + h * HEAD_DIM;
    uint32_t* o1 = o0 + 8 * D_MODEL;
    #pragma unroll
    for (int nt = 0; nt < 8; nt++) {
        *(uint2*)&o0[nt * 8 + 2 * qc] =
            make_uint2(f2tf(oacc[nt][0] * inv0), f2tf(oacc[nt][1] * inv0));
        *(uint2*)&o1[nt * 8 + 2 * qc] =
            make_uint2(f2tf(oacc[nt][2] * inv1), f2tf(oacc[nt][3] * inv1));
    }
}

// ---------------------------------------------------------------------------
extern "C" void kernel_launch(void* const* d_in, const int* in_sizes, int n_in,
                              void* d_out, int out_size)
{
    const float* x     = (const float*)d_in[0];
    const float* W_qkv = (const float*)d_in[1];
    const float* b_qkv = (const float*)d_in[2];
    const float* W_out = (const float*)d_in[3];
    const float* b_out = (const float*)d_in[4];
    float* out = (float*)d_out;

    const int gemm_smem  = 4 * 128 * 20 * 4;                       // 40960
    const int flash_smem = (64 * 68 + 64 * 68 + 128 * 68) * 4;     // 69632
    cudaFuncSetAttribute(tgemm3<0>, cudaFuncAttributeMaxDynamicSharedMemorySize, gemm_smem);
    cudaFuncSetAttribute(tgemm3<1>, cudaFuncAttributeMaxDynamicSharedMemorySize, gemm_smem);
    cudaFuncSetAttribute(flash_tc_kernel, cudaFuncAttributeMaxDynamicSharedMemorySize, flash_smem);

    uint32_t *x32, *w1t, *w2t, *ao;
    cudaGetSymbolAddress((void**)&x32, g_x32);
    cudaGetSymbolAddress((void**)&w1t, g_w1t);
    cudaGetSymbolAddress((void**)&w2t, g_w2t);
    cudaGetSymbolAddress((void**)&ao,  g_AO);

    // 0) pre-convert: x -> tf32; weights -> transposed [N][K] tf32
    {
        int n4 = MROWS * D_MODEL / 4;
        cvt_tf32_kernel<<<(n4 + 255) / 256, 256>>>((const float4*)x, (uint4*)x32, n4);
        cvt_transpose_tf32<<<dim3(QKV_N / 32, D_MODEL / 32), dim3(32, 8)>>>(
            W_qkv, w1t, D_MODEL, QKV_N);
        cvt_transpose_tf32<<<dim3(D_MODEL / 32, D_MODEL / 32), dim3(32, 8)>>>(
            W_out, w2t, D_MODEL, D_MODEL);
    }
    // 1) QKV projection -> g_Q / g_K (scaled) / g_V (tf32 bits)
    {
        dim3 grid(QKV_N / 128, MROWS / 128);    // (24, 64)
        tgemm3<1><<<grid, 256, gemm_smem>>>(x32, w1t, b_qkv, nullptr,
                                            MROWS, QKV_N, D_MODEL);
    }
    // 2) causal flash attention -> g_AO (tf32 bits)
    {
        dim3 grid(SEQ / 128, BATCH * N_HEADS);  // (16, 64)
        flash_tc_kernel<<<grid, 256, flash_smem>>>();
    }
    // 3) output projection -> d_out (fp32)
    {
        dim3 grid(D_MODEL / 128, MROWS / 128);  // (8, 64)
        tgemm3<0><<<grid, 256, gemm_smem>>>(ao, w2t, b_out, out,
                                            MROWS, D_MODEL, D_MODEL);
    }
}

// round 7
// speedup vs baseline: 3.4234x; 1.0233x over previous
#include <cuda_runtime.h>
#include <math.h>
#include <stdint.h>

#define D_MODEL 1024
#define N_HEADS 16
#define HEAD_DIM 64
#define BATCH 4
#define SEQ 2048
#define MROWS (BATCH * SEQ)          // 8192
#define QKV_N (3 * D_MODEL)          // 3072

// softmax scale folded into K at QKV epilogue: 1/sqrt(64) * log2(e)
#define KSCALE 0.18033688011111793f

// ---------------- scratch (__device__ globals) ------------------------------
__device__ __align__(16) uint32_t g_Q[BATCH * N_HEADS * SEQ * HEAD_DIM];
__device__ __align__(16) uint32_t g_K[BATCH * N_HEADS * SEQ * HEAD_DIM];
__device__ __align__(16) uint32_t g_V[BATCH * N_HEADS * SEQ * HEAD_DIM];
__device__ __align__(16) uint32_t g_AO[MROWS * D_MODEL];
__device__ __align__(16) uint32_t g_x32[MROWS * D_MODEL];
__device__ __align__(16) uint32_t g_w1t[QKV_N * D_MODEL];    // [N][K] tf32
__device__ __align__(16) uint32_t g_w2t[D_MODEL * D_MODEL];  // [N][K] tf32

// ---------------- helpers ----------------------------------------------------
__device__ __forceinline__ uint32_t smem_u32(const void* p) {
    uint32_t a;
    asm("{ .reg .u64 t; cvta.to.shared.u64 t, %1; cvt.u32.u64 %0, t; }"
        : "=r"(a) : "l"(p));
    return a;
}
__device__ __forceinline__ float ex2(float x) {
    float r; asm("ex2.approx.f32 %0, %1;" : "=f"(r) : "f"(x)); return r;
}
__device__ __forceinline__ uint32_t f2tf(float f) {
    uint32_t u; asm("cvt.rna.tf32.f32 %0, %1;" : "=r"(u) : "f"(f)); return u;
}
__device__ __forceinline__ void mma_tf32(float* d, const uint32_t* a,
                                         uint32_t b0, uint32_t b1) {
    asm volatile(
        "mma.sync.aligned.m16n8k8.row.col.f32.tf32.tf32.f32 "
        "{%0,%1,%2,%3}, {%4,%5,%6,%7}, {%8,%9}, {%0,%1,%2,%3};\n"
        : "+f"(d[0]), "+f"(d[1]), "+f"(d[2]), "+f"(d[3])
        : "r"(a[0]), "r"(a[1]), "r"(a[2]), "r"(a[3]), "r"(b0), "r"(b1));
}
#define LDSM4(r0, r1, r2, r3, addr) \
    asm volatile("ldmatrix.sync.aligned.m8n8.x4.shared.b16 {%0,%1,%2,%3}, [%4];" \
                 : "=r"(r0), "=r"(r1), "=r"(r2), "=r"(r3) : "r"(addr))
#define CP16(dst, src) \
    asm volatile("cp.async.cg.shared.global [%0], [%1], 16;" :: "r"(dst), "l"(src))
#define CP_COMMIT() asm volatile("cp.async.commit_group;")
#define CP_WAIT(n)  asm volatile("cp.async.wait_group %0;" :: "n"(n))

// ---------------------------------------------------------------------------
// Elementwise fp32 -> tf32 bits
// ---------------------------------------------------------------------------
__global__ __launch_bounds__(256)
void cvt_tf32_kernel(const float4* __restrict__ src, uint4* __restrict__ dst, int n4)
{
    int i = blockIdx.x * blockDim.x + threadIdx.x;
    if (i >= n4) return;
    float4 v = src[i];
    uint4 u;
    u.x = f2tf(v.x); u.y = f2tf(v.y); u.z = f2tf(v.z); u.w = f2tf(v.w);
    dst[i] = u;
}

// Transpose + convert: W[K][N] fp32 -> T[N][K] tf32 bits
__global__ __launch_bounds__(256)
void cvt_transpose_tf32(const float* __restrict__ W, uint32_t* __restrict__ T,
                        int K, int N)
{
    __shared__ float tile[32][33];
    const int k0 = blockIdx.y * 32, n0 = blockIdx.x * 32;
    const int tx = threadIdx.x, ty = threadIdx.y;     // 32 x 8
    #pragma unroll
    for (int i = 0; i < 32; i += 8)
        tile[ty + i][tx] = W[(size_t)(k0 + ty + i) * N + n0 + tx];
    __syncthreads();
    #pragma unroll
    for (int i = 0; i < 32; i += 8)
        T[(size_t)(n0 + ty + i) * K + k0 + tx] = f2tf(tile[tx][ty + i]);
}

// ---------------------------------------------------------------------------
// TF32 GEMM: C[M,N] = A[M,K] @ Bt[N,K]^T + bias.  128x128 tile, BK=16,
// 256 thr (8 warps, 4Mx2N, warp 32x64), 3-stage cp.async ring (1 sync/tile),
// ldmatrix fragments.
// MODE 0: fp32 C.  MODE 1: scatter tf32 bits into g_Q/g_K(*KSCALE)/g_V.
// ---------------------------------------------------------------------------
template <int MODE>
__global__ __launch_bounds__(256, 2)
void tgemm4(const uint32_t* __restrict__ A, const uint32_t* __restrict__ Bt,
            const float* __restrict__ bias, float* __restrict__ C,
            int M, int N, int K)
{
    constexpr int AST = 20;              // row stride (uint32), ldmatrix-conflict-free
    constexpr int TB  = 128 * AST;       // uint32 per operand per stage

    extern __shared__ __align__(16) uint32_t sm[];
    const uint32_t sA = smem_u32(sm);
    const uint32_t sB = sA + 3 * TB * 4;

    const int tid  = threadIdx.x;
    const int wid  = tid >> 5;
    const int lane = tid & 31;
    const int qr   = lane >> 2;
    const int qc   = lane & 3;
    const int wm   = wid >> 1;           // 0..3 (32 rows)
    const int wn   = wid & 1;            // 0..1 (64 cols)

    const int row0 = blockIdx.y * 128;
    const int col0 = blockIdx.x * 128;

    // cp.async coords: thread covers one half-row (8 k) of A and of Bt
    const int lr = tid >> 1, lh = (tid & 1) * 8;
    const uint32_t* aS0 = A  + (size_t)(row0 + lr) * K + lh;
    const uint32_t* bS0 = Bt + (size_t)(col0 + lr) * K + lh;
    const uint32_t aD0 = sA + (lr * AST + lh) * 4;
    const uint32_t bD0 = sB + (lr * AST + lh) * 4;

    // ldmatrix lane addressing
    const int a_row = wm * 32 + (lane & 7) + ((lane >> 3) & 1) * 8;
    const int a_col = (lane >> 4) * 4;
    const int b_row = wn * 64 + (lane >> 4) * 8 + (lane & 7);
    const int b_col = ((lane >> 3) & 1) * 4;

    float acc[2][8][4] = {};
    const int NK = K / 16;

    auto load_tile = [&](int kt, int s) {
        const uint32_t* as = aS0 + kt * 16;
        const uint32_t* bs = bS0 + kt * 16;
        const uint32_t ad = aD0 + s * TB * 4;
        const uint32_t bd = bD0 + s * TB * 4;
        CP16(ad, as); CP16(ad + 16, as + 4);
        CP16(bd, bs); CP16(bd + 16, bs + 4);
        CP_COMMIT();
    };

    load_tile(0, 0);
    load_tile(1, 1);

    for (int kt = 0; kt < NK; kt++) {
        if (kt + 1 < NK) { CP_WAIT(1); } else { CP_WAIT(0); }
        __syncthreads();
        if (kt + 2 < NK) load_tile(kt + 2, (kt + 2) % 3);

        const int cur = kt % 3;
        const uint32_t ab = sA + cur * TB * 4;
        const uint32_t bb = sB + cur * TB * 4;
        #pragma unroll
        for (int ks = 0; ks < 2; ks++) {
            uint32_t af[2][4], bf[8][2];
            #pragma unroll
            for (int mt = 0; mt < 2; mt++)
                LDSM4(af[mt][0], af[mt][1], af[mt][2], af[mt][3],
                      ab + (((a_row + mt * 16) * AST) + ks * 8 + a_col) * 4);
            #pragma unroll
            for (int np = 0; np < 4; np++)
                LDSM4(bf[np * 2][0], bf[np * 2][1], bf[np * 2 + 1][0], bf[np * 2 + 1][1],
                      bb + (((b_row + np * 16) * AST) + ks * 8 + b_col) * 4);
            #pragma unroll
            for (int mt = 0; mt < 2; mt++)
                #pragma unroll
                for (int nt = 0; nt < 8; nt++)
                    mma_tf32(acc[mt][nt], af[mt], bf[nt][0], bf[nt][1]);
        }
        // no trailing sync: next iteration's top sync protects buffer reuse
    }

    // epilogue
    #pragma unroll
    for (int mt = 0; mt < 2; mt++) {
        const int r = row0 + wm * 32 + mt * 16 + qr;
        #pragma unroll
        for (int nt = 0; nt < 8; nt++) {
            const int c = col0 + wn * 64 + nt * 8 + 2 * qc;
            const float bz0 = bias[c], bz1 = bias[c + 1];
            const float v00 = acc[mt][nt][0] + bz0;
            const float v01 = acc[mt][nt][1] + bz1;
            const float v10 = acc[mt][nt][2] + bz0;
            const float v11 = acc[mt][nt][3] + bz1;
            if (MODE == 0) {
                *(float2*)&C[(size_t)r * N + c]       = make_float2(v00, v01);
                *(float2*)&C[(size_t)(r + 8) * N + c] = make_float2(v10, v11);
            } else {
                const int sec = c >> 10, cc = c & 1023;
                const int h = cc >> 6, d = cc & 63;
                const int b = r >> 11, t = r & 2047;
                const float sc = (sec == 1) ? KSCALE : 1.0f;
                uint32_t* dst = (sec == 0 ? g_Q : sec == 1 ? g_K : g_V);
                const size_t off = ((size_t)(b * N_HEADS + h) * SEQ + t) * HEAD_DIM + d;
                *(uint2*)&dst[off] = make_uint2(f2tf(v00 * sc), f2tf(v01 * sc));
                *(uint2*)&dst[off + 8 * HEAD_DIM] =
                    make_uint2(f2tf(v10 * sc), f2tf(v11 * sc));
            }
        }
    }
}

// ---------------------------------------------------------------------------
// TF32 flash attention, causal.  128 q rows (8 warps x 16), K-tile 64.
// Double-buffered K (cp.async) + V (transposed scalar stores), 1 sync/tile;
// tile t+1 loads overlap tile t compute.  Heavy q-tiles scheduled first.
// ---------------------------------------------------------------------------
__global__ __launch_bounds__(256)
void flash_tc_kernel()
{
    constexpr int KST = 68;
    constexpr int PST = 68;
    constexpr int KB  = 64 * KST * 4;   // 17408 bytes per K/V buffer

    extern __shared__ __align__(16) char smemc[];
    uint32_t* Vsm = (uint32_t*)(smemc + 2 * KB);       // 2 buffers after K's 2
    uint32_t* Psm = (uint32_t*)(smemc + 4 * KB);
    const uint32_t sK = smem_u32(smemc);
    const uint32_t sV = sK + 2 * KB;
    const uint32_t sP = sK + 4 * KB;

    const int bh   = blockIdx.y;
    const int qx   = gridDim.x - 1 - blockIdx.x;       // heavy tiles first
    const int tid  = threadIdx.x;
    const int wid  = tid >> 5;
    const int lane = tid & 31;
    const int qr   = lane >> 2;
    const int qc   = lane & 3;

    const uint32_t* Qb = g_Q + (size_t)bh * SEQ * HEAD_DIM;
    const uint32_t* Kb = g_K + (size_t)bh * SEQ * HEAD_DIM;
    const uint32_t* Vb = g_V + (size_t)bh * SEQ * HEAD_DIM;

    const int rowbase = qx * 128 + wid * 16;

    // persistent Q fragments (raw tf32 bits; scale folded into K)
    uint32_t qf[8][4];
    {
        const uint32_t* r0 = Qb + (size_t)(rowbase + qr) * HEAD_DIM;
        const uint32_t* r1 = r0 + 8 * HEAD_DIM;
        #pragma unroll
        for (int kc = 0; kc < 8; kc++) {
            qf[kc][0] = r0[kc * 8 + qc];
            qf[kc][1] = r1[kc * 8 + qc];
            qf[kc][2] = r0[kc * 8 + qc + 4];
            qf[kc][3] = r1[kc * 8 + qc + 4];
        }
    }

    float oacc[8][4] = {};
    float m0 = -1e30f, m1 = -1e30f, l0 = 0.f, l1 = 0.f;

    const int nkt = 2 * (qx + 1);
    const int firstMasked = 2 * qx;

    // loader coords
    const int ldkey = tid >> 2;          // K cp.async: key row
    const int ldch  = tid & 3;
    const int vkey  = tid & 63;          // V transpose
    const int vdq   = tid >> 6;

    // ldmatrix lane addressing (B-pattern on K/Vt; A-pattern on P)
    const int nb_row = (lane >> 4) * 8 + (lane & 7);
    const int nb_col = ((lane >> 3) & 1) * 4;
    const int p_row  = wid * 16 + (lane & 7) + ((lane >> 3) & 1) * 8;
    const int p_col  = (lane >> 4) * 4;

    auto load_K = [&](int kt, int buf) {
        const uint32_t kD = sK + buf * KB + ldkey * (KST * 4) + ldch * 16;
        const uint32_t* kS = Kb + (size_t)(kt * 64 + ldkey) * HEAD_DIM + ldch * 4;
        #pragma unroll
        for (int i = 0; i < 4; i++) CP16(kD + i * 64, kS + i * 16);
        CP_COMMIT();
    };
    auto load_V = [&](int kt, int buf) {
        uint32_t* vd = Vsm + buf * (64 * KST);
        const uint32_t* vS = Vb + (size_t)(kt * 64 + vkey) * HEAD_DIM;
        #pragma unroll
        for (int i = 0; i < 4; i++) {
            uint4 v = *(const uint4*)(vS + (vdq + i * 4) * 4);
            const int d0 = (vdq + i * 4) * 4;
            vd[(d0 + 0) * KST + vkey] = v.x;
            vd[(d0 + 1) * KST + vkey] = v.y;
            vd[(d0 + 2) * KST + vkey] = v.z;
            vd[(d0 + 3) * KST + vkey] = v.w;
        }
    };

    load_K(0, 0);
    load_V(0, 0);

    for (int kt = 0; kt < nkt; kt++) {
        const int cur = kt & 1;
        const int kb = kt * 64;

        CP_WAIT(0);
        __syncthreads();
        // overlap next tile's loads with this tile's compute
        if (kt + 1 < nkt) {
            load_K(kt + 1, cur ^ 1);
            load_V(kt + 1, cur ^ 1);
        }

        const uint32_t kbuf = sK + cur * KB;
        const uint32_t vbuf = sV + cur * KB;

        // ---- S = Q K^T ----
        float sa[8][4];
        #pragma unroll
        for (int nt = 0; nt < 8; nt++) {
            sa[nt][0] = 0.f; sa[nt][1] = 0.f; sa[nt][2] = 0.f; sa[nt][3] = 0.f;
        }
        #pragma unroll
        for (int kc = 0; kc < 8; kc++) {
            #pragma unroll
            for (int np = 0; np < 4; np++) {
                uint32_t r0, r1, r2, r3;
                LDSM4(r0, r1, r2, r3,
                      kbuf + (((np * 16 + nb_row) * KST) + kc * 8 + nb_col) * 4);
                mma_tf32(sa[np * 2],     qf[kc], r0, r1);
                mma_tf32(sa[np * 2 + 1], qf[kc], r2, r3);
            }
        }

        // ---- causal mask (diagonal tiles only) ----
        if (kt >= firstMasked) {
            const int r0g = rowbase + qr;
            const int r1g = r0g + 8;
            #pragma unroll
            for (int nt = 0; nt < 8; nt++) {
                const int cg = kb + nt * 8 + 2 * qc;
                if (cg     > r0g) sa[nt][0] = -1e30f;
                if (cg + 1 > r0g) sa[nt][1] = -1e30f;
                if (cg     > r1g) sa[nt][2] = -1e30f;
                if (cg + 1 > r1g) sa[nt][3] = -1e30f;
            }
        }

        // ---- online softmax (log2 domain) ----
        float t0 = -1e30f, t1 = -1e30f;
        #pragma unroll
        for (int nt = 0; nt < 8; nt++) {
            t0 = fmaxf(t0, fmaxf(sa[nt][0], sa[nt][1]));
            t1 = fmaxf(t1, fmaxf(sa[nt][2], sa[nt][3]));
        }
        t0 = fmaxf(t0, __shfl_xor_sync(0xffffffffu, t0, 1));
        t0 = fmaxf(t0, __shfl_xor_sync(0xffffffffu, t0, 2));
        t1 = fmaxf(t1, __shfl_xor_sync(0xffffffffu, t1, 1));
        t1 = fmaxf(t1, __shfl_xor_sync(0xffffffffu, t1, 2));

        const float mn0 = fmaxf(m0, t0);
        const float mn1 = fmaxf(m1, t1);
        const float c0 = ex2(m0 - mn0);
        const float c1 = ex2(m1 - mn1);
        l0 *= c0; l1 *= c1;
        #pragma unroll
        for (int nt = 0; nt < 8; nt++) {
            oacc[nt][0] *= c0; oacc[nt][1] *= c0;
            oacc[nt][2] *= c1; oacc[nt][3] *= c1;
        }

        float rs0 = 0.f, rs1 = 0.f;
        uint32_t* Pw0 = Psm + (size_t)(wid * 16 + qr) * PST;
        uint32_t* Pw1 = Pw0 + 8 * PST;
        #pragma unroll
        for (int nt = 0; nt < 8; nt++) {
            const float p00 = ex2(sa[nt][0] - mn0);
            const float p01 = ex2(sa[nt][1] - mn0);
            const float p10 = ex2(sa[nt][2] - mn1);
            const float p11 = ex2(sa[nt][3] - mn1);
            rs0 += p00 + p01;
            rs1 += p10 + p11;
            *(uint2*)&Pw0[nt * 8 + 2 * qc] = make_uint2(f2tf(p00), f2tf(p01));
            *(uint2*)&Pw1[nt * 8 + 2 * qc] = make_uint2(f2tf(p10), f2tf(p11));
        }
        rs0 += __shfl_xor_sync(0xffffffffu, rs0, 1);
        rs0 += __shfl_xor_sync(0xffffffffu, rs0, 2);
        rs1 += __shfl_xor_sync(0xffffffffu, rs1, 1);
        rs1 += __shfl_xor_sync(0xffffffffu, rs1, 2);
        l0 += rs0; l1 += rs1;
        m0 = mn0; m1 = mn1;

        __syncwarp();

        // ---- O += P V  (P A-frags + Vt B-frags via ldmatrix) ----
        #pragma unroll
        for (int kc = 0; kc < 8; kc++) {
            uint32_t pa[4];
            LDSM4(pa[0], pa[1], pa[2], pa[3],
                  sP + ((p_row * PST) + kc * 8 + p_col) * 4);
            #pragma unroll
            for (int np = 0; np < 4; np++) {
                uint32_t r0, r1, r2, r3;
                LDSM4(r0, r1, r2, r3,
                      vbuf + (((np * 16 + nb_row) * KST) + kc * 8 + nb_col) * 4);
                mma_tf32(oacc[np * 2],     pa, r0, r1);
                mma_tf32(oacc[np * 2 + 1], pa, r2, r3);
            }
        }
        // no trailing sync: next iteration's top sync protects buffers
    }

    // ---- epilogue: normalize, write tf32 bits to g_AO [B*T][C] ----
    const int b = bh >> 4;
    const int h = bh & 15;
    const float inv0 = 1.f / l0;
    const float inv1 = 1.f / l1;
    const int t0g = rowbase + qr;
    uint32_t* o0 = g_AO + ((size_t)(b * SEQ + t0g)) * D_MODEL + h * HEAD_DIM;
    uint32_t* o1 = o0 + 8 * D_MODEL;
    #pragma unroll
    for (int nt = 0; nt < 8; nt++) {
        *(uint2*)&o0[nt * 8 + 2 * qc] =
            make_uint2(f2tf(oacc[nt][0] * inv0), f2tf(oacc[nt][1] * inv0));
        *(uint2*)&o1[nt * 8 + 2 * qc] =
            make_uint2(f2tf(oacc[nt][2] * inv1), f2tf(oacc[nt][3] * inv1));
    }
}

// ---------------------------------------------------------------------------
extern "C" void kernel_launch(void* const* d_in, const int* in_sizes, int n_in,
                              void* d_out, int out_size)
{
    const float* x     = (const float*)d_in[0];
    const float* W_qkv = (const float*)d_in[1];
    const float* b_qkv = (const float*)d_in[2];
    const float* W_out = (const float*)d_in[3];
    const float* b_out = (const float*)d_in[4];
    float* out = (float*)d_out;

    const int gemm_smem  = 6 * 128 * 20 * 4;                   // 61440
    const int flash_smem = 4 * (64 * 68 * 4) + 128 * 68 * 4;   // 104448
    cudaFuncSetAttribute(tgemm4<0>, cudaFuncAttributeMaxDynamicSharedMemorySize, gemm_smem);
    cudaFuncSetAttribute(tgemm4<1>, cudaFuncAttributeMaxDynamicSharedMemorySize, gemm_smem);
    cudaFuncSetAttribute(flash_tc_kernel, cudaFuncAttributeMaxDynamicSharedMemorySize, flash_smem);

    uint32_t *x32, *w1t, *w2t, *ao;
    cudaGetSymbolAddress((void**)&x32, g_x32);
    cudaGetSymbolAddress((void**)&w1t, g_w1t);
    cudaGetSymbolAddress((void**)&w2t, g_w2t);
    cudaGetSymbolAddress((void**)&ao,  g_AO);

    // 0) pre-convert: x -> tf32; weights -> transposed [N][K] tf32
    {
        int n4 = MROWS * D_MODEL / 4;
        cvt_tf32_kernel<<<(n4 + 255) / 256, 256>>>((const float4*)x, (uint4*)x32, n4);
        cvt_transpose_tf32<<<dim3(QKV_N / 32, D_MODEL / 32), dim3(32, 8)>>>(
            W_qkv, w1t, D_MODEL, QKV_N);
        cvt_transpose_tf32<<<dim3(D_MODEL / 32, D_MODEL / 32), dim3(32, 8)>>>(
            W_out, w2t, D_MODEL, D_MODEL);
    }
    // 1) QKV projection -> g_Q / g_K (scaled) / g_V (tf32 bits)
    {
        dim3 grid(QKV_N / 128, MROWS / 128);    // (24, 64)
        tgemm4<1><<<grid, 256, gemm_smem>>>(x32, w1t, b_qkv, nullptr,
                                            MROWS, QKV_N, D_MODEL);
    }
    // 2) causal flash attention -> g_AO (tf32 bits)
    {
        dim3 grid(SEQ / 128, BATCH * N_HEADS);  // (16, 64)
        flash_tc_kernel<<<grid, 256, flash_smem>>>();
    }
    // 3) output projection -> d_out (fp32)
    {
        dim3 grid(D_MODEL / 128, MROWS / 128);  // (8, 64)
        tgemm4<0><<<grid, 256, gemm_smem>>>(ao, w2t, b_out, out,
                                            MROWS, D_MODEL, D_MODEL);
    }
}

// round 8
// speedup vs baseline: 3.5501x; 1.0370x over previous
#include <cuda_runtime.h>
#include <math.h>
#include <stdint.h>

#define D_MODEL 1024
#define N_HEADS 16
#define HEAD_DIM 64
#define BATCH 4
#define SEQ 2048
#define MROWS (BATCH * SEQ)          // 8192
#define QKV_N (3 * D_MODEL)          // 3072

// softmax scale folded into K at QKV epilogue: 1/sqrt(64) * log2(e)
#define KSCALE 0.18033688011111793f

// ---------------- scratch (__device__ globals) ------------------------------
__device__ __align__(16) uint32_t g_Q[BATCH * N_HEADS * SEQ * HEAD_DIM];
__device__ __align__(16) uint32_t g_K[BATCH * N_HEADS * SEQ * HEAD_DIM];
__device__ __align__(16) uint32_t g_V[BATCH * N_HEADS * SEQ * HEAD_DIM];
__device__ __align__(16) uint32_t g_AO[MROWS * D_MODEL];
__device__ __align__(16) uint32_t g_x32[MROWS * D_MODEL];
__device__ __align__(16) uint32_t g_w1t[QKV_N * D_MODEL];    // [N][K] tf32
__device__ __align__(16) uint32_t g_w2t[D_MODEL * D_MODEL];  // [N][K] tf32

// ---------------- helpers ----------------------------------------------------
__device__ __forceinline__ uint32_t smem_u32(const void* p) {
    uint32_t a;
    asm("{ .reg .u64 t; cvta.to.shared.u64 t, %1; cvt.u32.u64 %0, t; }"
        : "=r"(a) : "l"(p));
    return a;
}
__device__ __forceinline__ float ex2(float x) {
    float r; asm("ex2.approx.f32 %0, %1;" : "=f"(r) : "f"(x)); return r;
}
__device__ __forceinline__ uint32_t f2tf(float f) {
    uint32_t u; asm("cvt.rna.tf32.f32 %0, %1;" : "=r"(u) : "f"(f)); return u;
}
__device__ __forceinline__ void mma_tf32(float* d, const uint32_t* a,
                                         uint32_t b0, uint32_t b1) {
    asm volatile(
        "mma.sync.aligned.m16n8k8.row.col.f32.tf32.tf32.f32 "
        "{%0,%1,%2,%3}, {%4,%5,%6,%7}, {%8,%9}, {%0,%1,%2,%3};\n"
        : "+f"(d[0]), "+f"(d[1]), "+f"(d[2]), "+f"(d[3])
        : "r"(a[0]), "r"(a[1]), "r"(a[2]), "r"(a[3]), "r"(b0), "r"(b1));
}
#define LDSM4(r0, r1, r2, r3, addr) \
    asm volatile("ldmatrix.sync.aligned.m8n8.x4.shared.b16 {%0,%1,%2,%3}, [%4];" \
                 : "=r"(r0), "=r"(r1), "=r"(r2), "=r"(r3) : "r"(addr))
#define CP16(dst, src) \
    asm volatile("cp.async.cg.shared.global [%0], [%1], 16;" :: "r"(dst), "l"(src))
#define CP_COMMIT() asm volatile("cp.async.commit_group;")
#define CP_WAIT(n)  asm volatile("cp.async.wait_group %0;" :: "n"(n))

// ---------------------------------------------------------------------------
// Elementwise fp32 -> tf32 bits
// ---------------------------------------------------------------------------
__global__ __launch_bounds__(256)
void cvt_tf32_kernel(const float4* __restrict__ src, uint4* __restrict__ dst, int n4)
{
    int i = blockIdx.x * blockDim.x + threadIdx.x;
    if (i >= n4) return;
    float4 v = src[i];
    uint4 u;
    u.x = f2tf(v.x); u.y = f2tf(v.y); u.z = f2tf(v.z); u.w = f2tf(v.w);
    dst[i] = u;
}

// Transpose + convert: W[K][N] fp32 -> T[N][K] tf32 bits
__global__ __launch_bounds__(256)
void cvt_transpose_tf32(const float* __restrict__ W, uint32_t* __restrict__ T,
                        int K, int N)
{
    __shared__ float tile[32][33];
    const int k0 = blockIdx.y * 32, n0 = blockIdx.x * 32;
    const int tx = threadIdx.x, ty = threadIdx.y;     // 32 x 8
    #pragma unroll
    for (int i = 0; i < 32; i += 8)
        tile[ty + i][tx] = W[(size_t)(k0 + ty + i) * N + n0 + tx];
    __syncthreads();
    #pragma unroll
    for (int i = 0; i < 32; i += 8)
        T[(size_t)(n0 + ty + i) * K + k0 + tx] = f2tf(tile[tx][ty + i]);
}

// ---------------------------------------------------------------------------
// TF32 GEMM (unchanged from round 7): 128x128 tile, BK=16, 8 warps 32x64,
// 3-stage cp.async ring, ldmatrix fragments.
// ---------------------------------------------------------------------------
template <int MODE>
__global__ __launch_bounds__(256, 2)
void tgemm4(const uint32_t* __restrict__ A, const uint32_t* __restrict__ Bt,
            const float* __restrict__ bias, float* __restrict__ C,
            int M, int N, int K)
{
    constexpr int AST = 20;
    constexpr int TB  = 128 * AST;

    extern __shared__ __align__(16) uint32_t sm[];
    const uint32_t sA = smem_u32(sm);
    const uint32_t sB = sA + 3 * TB * 4;

    const int tid  = threadIdx.x;
    const int wid  = tid >> 5;
    const int lane = tid & 31;
    const int qr   = lane >> 2;
    const int qc   = lane & 3;
    const int wm   = wid >> 1;
    const int wn   = wid & 1;

    const int row0 = blockIdx.y * 128;
    const int col0 = blockIdx.x * 128;

    const int lr = tid >> 1, lh = (tid & 1) * 8;
    const uint32_t* aS0 = A  + (size_t)(row0 + lr) * K + lh;
    const uint32_t* bS0 = Bt + (size_t)(col0 + lr) * K + lh;
    const uint32_t aD0 = sA + (lr * AST + lh) * 4;
    const uint32_t bD0 = sB + (lr * AST + lh) * 4;

    const int a_row = wm * 32 + (lane & 7) + ((lane >> 3) & 1) * 8;
    const int a_col = (lane >> 4) * 4;
    const int b_row = wn * 64 + (lane >> 4) * 8 + (lane & 7);
    const int b_col = ((lane >> 3) & 1) * 4;

    float acc[2][8][4] = {};
    const int NK = K / 16;

    auto load_tile = [&](int kt, int s) {
        const uint32_t* as = aS0 + kt * 16;
        const uint32_t* bs = bS0 + kt * 16;
        const uint32_t ad = aD0 + s * TB * 4;
        const uint32_t bd = bD0 + s * TB * 4;
        CP16(ad, as); CP16(ad + 16, as + 4);
        CP16(bd, bs); CP16(bd + 16, bs + 4);
        CP_COMMIT();
    };

    load_tile(0, 0);
    load_tile(1, 1);

    for (int kt = 0; kt < NK; kt++) {
        if (kt + 1 < NK) { CP_WAIT(1); } else { CP_WAIT(0); }
        __syncthreads();
        if (kt + 2 < NK) load_tile(kt + 2, (kt + 2) % 3);

        const int cur = kt % 3;
        const uint32_t ab = sA + cur * TB * 4;
        const uint32_t bb = sB + cur * TB * 4;
        #pragma unroll
        for (int ks = 0; ks < 2; ks++) {
            uint32_t af[2][4], bf[8][2];
            #pragma unroll
            for (int mt = 0; mt < 2; mt++)
                LDSM4(af[mt][0], af[mt][1], af[mt][2], af[mt][3],
                      ab + (((a_row + mt * 16) * AST) + ks * 8 + a_col) * 4);
            #pragma unroll
            for (int np = 0; np < 4; np++)
                LDSM4(bf[np * 2][0], bf[np * 2][1], bf[np * 2 + 1][0], bf[np * 2 + 1][1],
                      bb + (((b_row + np * 16) * AST) + ks * 8 + b_col) * 4);
            #pragma unroll
            for (int mt = 0; mt < 2; mt++)
                #pragma unroll
                for (int nt = 0; nt < 8; nt++)
                    mma_tf32(acc[mt][nt], af[mt], bf[nt][0], bf[nt][1]);
        }
    }

    #pragma unroll
    for (int mt = 0; mt < 2; mt++) {
        const int r = row0 + wm * 32 + mt * 16 + qr;
        #pragma unroll
        for (int nt = 0; nt < 8; nt++) {
            const int c = col0 + wn * 64 + nt * 8 + 2 * qc;
            const float bz0 = bias[c], bz1 = bias[c + 1];
            const float v00 = acc[mt][nt][0] + bz0;
            const float v01 = acc[mt][nt][1] + bz1;
            const float v10 = acc[mt][nt][2] + bz0;
            const float v11 = acc[mt][nt][3] + bz1;
            if (MODE == 0) {
                *(float2*)&C[(size_t)r * N + c]       = make_float2(v00, v01);
                *(float2*)&C[(size_t)(r + 8) * N + c] = make_float2(v10, v11);
            } else {
                const int sec = c >> 10, cc = c & 1023;
                const int h = cc >> 6, d = cc & 63;
                const int b = r >> 11, t = r & 2047;
                const float sc = (sec == 1) ? KSCALE : 1.0f;
                uint32_t* dst = (sec == 0 ? g_Q : sec == 1 ? g_K : g_V);
                const size_t off = ((size_t)(b * N_HEADS + h) * SEQ + t) * HEAD_DIM + d;
                *(uint2*)&dst[off] = make_uint2(f2tf(v00 * sc), f2tf(v01 * sc));
                *(uint2*)&dst[off + 8 * HEAD_DIM] =
                    make_uint2(f2tf(v10 * sc), f2tf(v11 * sc));
            }
        }
    }
}

// ---------------------------------------------------------------------------
// TF32 flash attention, causal.  128 q rows, 4 warps x 32 rows (2x m16 tiles
// per warp) -> K/V fragments reused across both sub-tiles, halving crossbar
// traffic per q-row.  Double-buffered K/V, 1 sync/tile, heavy tiles first.
// ---------------------------------------------------------------------------
__global__ __launch_bounds__(128, 2)
void flash_tc_kernel()
{
    constexpr int KST = 68;
    constexpr int PST = 68;
    constexpr int KB  = 64 * KST * 4;   // bytes per K/V buffer

    extern __shared__ __align__(16) char smemc[];
    uint32_t* Vsm = (uint32_t*)(smemc + 2 * KB);
    const uint32_t sK = smem_u32(smemc);
    const uint32_t sV = sK + 2 * KB;
    const uint32_t sP = sK + 4 * KB;

    const int bh   = blockIdx.y;
    const int qx   = gridDim.x - 1 - blockIdx.x;       // heavy tiles first
    const int tid  = threadIdx.x;
    const int wid  = tid >> 5;                         // 0..3
    const int lane = tid & 31;
    const int qr   = lane >> 2;
    const int qc   = lane & 3;

    const uint32_t* Qb = g_Q + (size_t)bh * SEQ * HEAD_DIM;
    const uint32_t* Kb = g_K + (size_t)bh * SEQ * HEAD_DIM;
    const uint32_t* Vb = g_V + (size_t)bh * SEQ * HEAD_DIM;

    const int rowbase = qx * 128 + wid * 32;           // warp owns 32 rows

    // persistent Q fragments: 2 m16 sub-tiles
    uint32_t qf[2][8][4];
    #pragma unroll
    for (int mt = 0; mt < 2; mt++) {
        const uint32_t* r0 = Qb + (size_t)(rowbase + mt * 16 + qr) * HEAD_DIM;
        const uint32_t* r1 = r0 + 8 * HEAD_DIM;
        #pragma unroll
        for (int kc = 0; kc < 8; kc++) {
            qf[mt][kc][0] = r0[kc * 8 + qc];
            qf[mt][kc][1] = r1[kc * 8 + qc];
            qf[mt][kc][2] = r0[kc * 8 + qc + 4];
            qf[mt][kc][3] = r1[kc * 8 + qc + 4];
        }
    }

    float oacc[2][8][4] = {};
    float mm[2][2] = {{-1e30f, -1e30f}, {-1e30f, -1e30f}};
    float ll[2][2] = {{0.f, 0.f}, {0.f, 0.f}};

    const int nkt = 2 * (qx + 1);
    const int firstMasked = 2 * qx;

    // loader coords (128 threads)
    const int ldkey = tid >> 1;          // K: 0..63
    const int ldch  = (tid & 1) * 8;     // 8 of 16 16B chunks per row
    const int vkey  = tid & 63;          // V transpose
    const int vdq   = tid >> 6;          // 0..1

    // ldmatrix lane addressing (B-pattern on K/Vt; A-pattern on P)
    const int nb_row = (lane >> 4) * 8 + (lane & 7);
    const int nb_col = ((lane >> 3) & 1) * 4;
    const int p_rw   = wid * 32 + (lane & 7) + ((lane >> 3) & 1) * 8;
    const int p_col  = (lane >> 4) * 4;

    auto load_K = [&](int kt, int buf) {
        const uint32_t kD = sK + buf * KB + ldkey * (KST * 4) + ldch * 16;
        const uint32_t* kS = Kb + (size_t)(kt * 64 + ldkey) * HEAD_DIM + ldch * 4;
        #pragma unroll
        for (int i = 0; i < 8; i++) CP16(kD + i * 16, kS + i * 4);
        CP_COMMIT();
    };
    auto load_V = [&](int kt, int buf) {
        uint32_t* vd = Vsm + buf * (64 * KST);
        const uint32_t* vS = Vb + (size_t)(kt * 64 + vkey) * HEAD_DIM;
        #pragma unroll
        for (int i = 0; i < 8; i++) {
            const int d4 = vdq + i * 2;            // 0..15
            uint4 v = *(const uint4*)(vS + d4 * 4);
            const int d0 = d4 * 4;
            vd[(d0 + 0) * KST + vkey] = v.x;
            vd[(d0 + 1) * KST + vkey] = v.y;
            vd[(d0 + 2) * KST + vkey] = v.z;
            vd[(d0 + 3) * KST + vkey] = v.w;
        }
    };

    load_K(0, 0);
    load_V(0, 0);

    for (int kt = 0; kt < nkt; kt++) {
        const int cur = kt & 1;
        const int kb = kt * 64;

        CP_WAIT(0);
        __syncthreads();
        if (kt + 1 < nkt) {
            load_K(kt + 1, cur ^ 1);
            load_V(kt + 1, cur ^ 1);
        }

        const uint32_t kbuf = sK + cur * KB;
        const uint32_t vbuf = sV + cur * KB;

        // ---- S = Q K^T : one K-frag feeds both m16 sub-tiles ----
        float sa[2][8][4];
        #pragma unroll
        for (int mt = 0; mt < 2; mt++)
            #pragma unroll
            for (int nt = 0; nt < 8; nt++) {
                sa[mt][nt][0] = 0.f; sa[mt][nt][1] = 0.f;
                sa[mt][nt][2] = 0.f; sa[mt][nt][3] = 0.f;
            }
        #pragma unroll
        for (int kc = 0; kc < 8; kc++) {
            #pragma unroll
            for (int np = 0; np < 4; np++) {
                uint32_t r0, r1, r2, r3;
                LDSM4(r0, r1, r2, r3,
                      kbuf + (((np * 16 + nb_row) * KST) + kc * 8 + nb_col) * 4);
                mma_tf32(sa[0][np * 2],     qf[0][kc], r0, r1);
                mma_tf32(sa[0][np * 2 + 1], qf[0][kc], r2, r3);
                mma_tf32(sa[1][np * 2],     qf[1][kc], r0, r1);
                mma_tf32(sa[1][np * 2 + 1], qf[1][kc], r2, r3);
            }
        }

        // ---- mask + online softmax + P store, per sub-tile ----
        #pragma unroll
        for (int mt = 0; mt < 2; mt++) {
            if (kt >= firstMasked) {
                const int r0g = rowbase + mt * 16 + qr;
                const int r1g = r0g + 8;
                #pragma unroll
                for (int nt = 0; nt < 8; nt++) {
                    const int cg = kb + nt * 8 + 2 * qc;
                    if (cg     > r0g) sa[mt][nt][0] = -1e30f;
                    if (cg + 1 > r0g) sa[mt][nt][1] = -1e30f;
                    if (cg     > r1g) sa[mt][nt][2] = -1e30f;
                    if (cg + 1 > r1g) sa[mt][nt][3] = -1e30f;
                }
            }

            float t0 = -1e30f, t1 = -1e30f;
            #pragma unroll
            for (int nt = 0; nt < 8; nt++) {
                t0 = fmaxf(t0, fmaxf(sa[mt][nt][0], sa[mt][nt][1]));
                t1 = fmaxf(t1, fmaxf(sa[mt][nt][2], sa[mt][nt][3]));
            }
            t0 = fmaxf(t0, __shfl_xor_sync(0xffffffffu, t0, 1));
            t0 = fmaxf(t0, __shfl_xor_sync(0xffffffffu, t0, 2));
            t1 = fmaxf(t1, __shfl_xor_sync(0xffffffffu, t1, 1));
            t1 = fmaxf(t1, __shfl_xor_sync(0xffffffffu, t1, 2));

            const float mn0 = fmaxf(mm[mt][0], t0);
            const float mn1 = fmaxf(mm[mt][1], t1);
            const float c0 = ex2(mm[mt][0] - mn0);
            const float c1 = ex2(mm[mt][1] - mn1);
            ll[mt][0] *= c0; ll[mt][1] *= c1;
            #pragma unroll
            for (int nt = 0; nt < 8; nt++) {
                oacc[mt][nt][0] *= c0; oacc[mt][nt][1] *= c0;
                oacc[mt][nt][2] *= c1; oacc[mt][nt][3] *= c1;
            }

            float rs0 = 0.f, rs1 = 0.f;
            uint32_t* Pw0 = (uint32_t*)(smemc + (sP - sK)) +
                            (size_t)(wid * 32 + mt * 16 + qr) * PST;
            uint32_t* Pw1 = Pw0 + 8 * PST;
            #pragma unroll
            for (int nt = 0; nt < 8; nt++) {
                const float p00 = ex2(sa[mt][nt][0] - mn0);
                const float p01 = ex2(sa[mt][nt][1] - mn0);
                const float p10 = ex2(sa[mt][nt][2] - mn1);
                const float p11 = ex2(sa[mt][nt][3] - mn1);
                rs0 += p00 + p01;
                rs1 += p10 + p11;
                *(uint2*)&Pw0[nt * 8 + 2 * qc] = make_uint2(f2tf(p00), f2tf(p01));
                *(uint2*)&Pw1[nt * 8 + 2 * qc] = make_uint2(f2tf(p10), f2tf(p11));
            }
            rs0 += __shfl_xor_sync(0xffffffffu, rs0, 1);
            rs0 += __shfl_xor_sync(0xffffffffu, rs0, 2);
            rs1 += __shfl_xor_sync(0xffffffffu, rs1, 1);
            rs1 += __shfl_xor_sync(0xffffffffu, rs1, 2);
            ll[mt][0] += rs0; ll[mt][1] += rs1;
            mm[mt][0] = mn0; mm[mt][1] = mn1;
        }

        __syncwarp();

        // ---- O += P V : one V-frag feeds both sub-tiles ----
        #pragma unroll
        for (int kc = 0; kc < 8; kc++) {
            uint32_t pa[2][4];
            #pragma unroll
            for (int mt = 0; mt < 2; mt++)
                LDSM4(pa[mt][0], pa[mt][1], pa[mt][2], pa[mt][3],
                      sP + (((p_rw + mt * 16) * PST) + kc * 8 + p_col) * 4);
            #pragma unroll
            for (int np = 0; np < 4; np++) {
                uint32_t r0, r1, r2, r3;
                LDSM4(r0, r1, r2, r3,
                      vbuf + (((np * 16 + nb_row) * KST) + kc * 8 + nb_col) * 4);
                mma_tf32(oacc[0][np * 2],     pa[0], r0, r1);
                mma_tf32(oacc[0][np * 2 + 1], pa[0], r2, r3);
                mma_tf32(oacc[1][np * 2],     pa[1], r0, r1);
                mma_tf32(oacc[1][np * 2 + 1], pa[1], r2, r3);
            }
        }
    }

    // ---- epilogue: normalize, write tf32 bits to g_AO [B*T][C] ----
    const int b = bh >> 4;
    const int h = bh & 15;
    #pragma unroll
    for (int mt = 0; mt < 2; mt++) {
        const float inv0 = 1.f / ll[mt][0];
        const float inv1 = 1.f / ll[mt][1];
        const int t0g = rowbase + mt * 16 + qr;
        uint32_t* o0 = g_AO + ((size_t)(b * SEQ + t0g)) * D_MODEL + h * HEAD_DIM;
        uint32_t* o1 = o0 + 8 * D_MODEL;
        #pragma unroll
        for (int nt = 0; nt < 8; nt++) {
            *(uint2*)&o0[nt * 8 + 2 * qc] =
                make_uint2(f2tf(oacc[mt][nt][0] * inv0), f2tf(oacc[mt][nt][1] * inv0));
            *(uint2*)&o1[nt * 8 + 2 * qc] =
                make_uint2(f2tf(oacc[mt][nt][2] * inv1), f2tf(oacc[mt][nt][3] * inv1));
        }
    }
}

// ---------------------------------------------------------------------------
extern "C" void kernel_launch(void* const* d_in, const int* in_sizes, int n_in,
                              void* d_out, int out_size)
{
    const float* x     = (const float*)d_in[0];
    const float* W_qkv = (const float*)d_in[1];
    const float* b_qkv = (const float*)d_in[2];
    const float* W_out = (const float*)d_in[3];
    const float* b_out = (const float*)d_in[4];
    float* out = (float*)d_out;

    const int gemm_smem  = 6 * 128 * 20 * 4;                   // 61440
    const int flash_smem = 4 * (64 * 68 * 4) + 128 * 68 * 4;   // 104448
    cudaFuncSetAttribute(tgemm4<0>, cudaFuncAttributeMaxDynamicSharedMemorySize, gemm_smem);
    cudaFuncSetAttribute(tgemm4<1>, cudaFuncAttributeMaxDynamicSharedMemorySize, gemm_smem);
    cudaFuncSetAttribute(flash_tc_kernel, cudaFuncAttributeMaxDynamicSharedMemorySize, flash_smem);

    uint32_t *x32, *w1t, *w2t, *ao;
    cudaGetSymbolAddress((void**)&x32, g_x32);
    cudaGetSymbolAddress((void**)&w1t, g_w1t);
    cudaGetSymbolAddress((void**)&w2t, g_w2t);
    cudaGetSymbolAddress((void**)&ao,  g_AO);

    // 0) pre-convert: x -> tf32; weights -> transposed [N][K] tf32
    {
        int n4 = MROWS * D_MODEL / 4;
        cvt_tf32_kernel<<<(n4 + 255) / 256, 256>>>((const float4*)x, (uint4*)x32, n4);
        cvt_transpose_tf32<<<dim3(QKV_N / 32, D_MODEL / 32), dim3(32, 8)>>>(
            W_qkv, w1t, D_MODEL, QKV_N);
        cvt_transpose_tf32<<<dim3(D_MODEL / 32, D_MODEL / 32), dim3(32, 8)>>>(
            W_out, w2t, D_MODEL, D_MODEL);
    }
    // 1) QKV projection -> g_Q / g_K (scaled) / g_V (tf32 bits)
    {
        dim3 grid(QKV_N / 128, MROWS / 128);    // (24, 64)
        tgemm4<1><<<grid, 256, gemm_smem>>>(x32, w1t, b_qkv, nullptr,
                                            MROWS, QKV_N, D_MODEL);
    }
    // 2) causal flash attention -> g_AO (tf32 bits)
    {
        dim3 grid(SEQ / 128, BATCH * N_HEADS);  // (16, 64)
        flash_tc_kernel<<<grid, 128, flash_smem>>>();
    }
    // 3) output projection -> d_out (fp32)
    {
        dim3 grid(D_MODEL / 128, MROWS / 128);  // (8, 64)
        tgemm4<0><<<grid, 256, gemm_smem>>>(ao, w2t, b_out, out,
                                            MROWS, D_MODEL, D_MODEL);
    }
}